// round 8
// baseline (speedup 1.0000x reference)
#include <cuda_runtime.h>
#include <cuda_bf16.h>
#include <math.h>
#include <stdint.h>

// ---------------- problem constants ----------------
#define DMODEL 1024
#define DSTATE 128
#define LSEQ   4096
#define NBATCH 4
#define MROWS  (NBATCH * LSEQ)   // 16384
#define LN_EPS 1e-3f

#define CHUNK  64
#define NCHUNK (LSEQ / CHUNK)    // 64
#define NCAT   512               // padded 3*128 fused projection width

// ---------------- portable PTX helpers (sm_80+ features only) ----------------
__device__ __forceinline__ uint32_t smem_to_u32(const void* smem_ptr) {
    uint32_t addr;
    asm("{ .reg .u64 tmp; cvta.to.shared.u64 tmp, %1; cvt.u32.u64 %0, tmp; }"
        : "=r"(addr) : "l"(smem_ptr));
    return addr;
}

#define CP_ASYNC16(smem_u32, gptr) \
    asm volatile("cp.async.cg.shared.global [%0], [%1], 16;" \
        :: "r"(smem_u32), "l"(gptr) : "memory")
#define CP_COMMIT() asm volatile("cp.async.commit_group;" ::: "memory")

template <int N>
__device__ __forceinline__ void cp_wait() {
    asm volatile("cp.async.wait_group %0;" :: "n"(N) : "memory");
}

__device__ __forceinline__ void ldsm4(uint32_t addr, uint32_t* r) {
    asm volatile("ldmatrix.sync.aligned.m8n8.x4.shared.b16 {%0,%1,%2,%3}, [%4];"
        : "=r"(r[0]), "=r"(r[1]), "=r"(r[2]), "=r"(r[3]) : "r"(addr));
}

__device__ __forceinline__ void mma16816(float* c, const uint32_t* a, const uint32_t* b) {
    asm volatile(
        "mma.sync.aligned.m16n8k16.row.col.f32.bf16.bf16.f32 "
        "{%0,%1,%2,%3}, {%4,%5,%6,%7}, {%8,%9}, {%0,%1,%2,%3};"
        : "+f"(c[0]), "+f"(c[1]), "+f"(c[2]), "+f"(c[3])
        : "r"(a[0]), "r"(a[1]), "r"(a[2]), "r"(a[3]), "r"(b[0]), "r"(b[1]));
}

__device__ __forceinline__ void split1(float v, __nv_bfloat16& h, __nv_bfloat16& l) {
    h = __float2bfloat16_rn(v);
    l = __float2bfloat16_rn(v - __bfloat162float(h));
}

// ---------------- scratch (static device globals; no allocation) ----------------
__device__ float g_z   [(size_t)MROWS * DMODEL];
__device__ float g_zcat[(size_t)MROWS * NCAT];
__device__ float g_yloc[(size_t)MROWS * DSTATE];
__device__ float g_carry[NBATCH * NCHUNK * DSTATE];
// bf16-split activations
__device__ __nv_bfloat16 g_xnh[(size_t)MROWS * DMODEL];
__device__ __nv_bfloat16 g_xnl[(size_t)MROWS * DMODEL];
__device__ __nv_bfloat16 g_zh [(size_t)MROWS * DMODEL];
__device__ __nv_bfloat16 g_zl [(size_t)MROWS * DMODEL];
__device__ __nv_bfloat16 g_yh [(size_t)MROWS * DMODEL];
__device__ __nv_bfloat16 g_yl [(size_t)MROWS * DMODEL];
__device__ __nv_bfloat16 g_ysh[(size_t)MROWS * DSTATE];
__device__ __nv_bfloat16 g_ysl[(size_t)MROWS * DSTATE];
// pre-transposed, bf16-split weights ([N, K] layout, K-major)
__device__ __nv_bfloat16 g_WinT_h [(size_t)DMODEL * DMODEL];
__device__ __nv_bfloat16 g_WinT_l [(size_t)DMODEL * DMODEL];
__device__ __nv_bfloat16 g_WoutT_h[(size_t)DMODEL * DMODEL];
__device__ __nv_bfloat16 g_WoutT_l[(size_t)DMODEL * DMODEL];
__device__ __nv_bfloat16 g_WsoT_h [(size_t)DMODEL * DSTATE];
__device__ __nv_bfloat16 g_WsoT_l [(size_t)DMODEL * DSTATE];
__device__ __nv_bfloat16 g_WcatT_h[(size_t)NCAT * DMODEL];
__device__ __nv_bfloat16 g_WcatT_l[(size_t)NCAT * DMODEL];
__device__ float g_bcat[NCAT];

// ---------------- LayerNorm (emits bf16 h/l split directly) ----------------
__global__ void ln_kernel(const float* __restrict__ x,
                          const float* __restrict__ gamma,
                          const float* __restrict__ beta,
                          __nv_bfloat16* __restrict__ oh,
                          __nv_bfloat16* __restrict__ ol)
{
    int row = blockIdx.x;
    const float4* xr = (const float4*)(x + (size_t)row * DMODEL);
    float4 v = xr[threadIdx.x];
    float s = v.x + v.y + v.z + v.w;
    float q = v.x * v.x + v.y * v.y + v.z * v.z + v.w * v.w;
    #pragma unroll
    for (int o = 16; o; o >>= 1) {
        s += __shfl_xor_sync(0xffffffffu, s, o);
        q += __shfl_xor_sync(0xffffffffu, q, o);
    }
    __shared__ float ss[8], sq[8];
    int w = threadIdx.x >> 5;
    if ((threadIdx.x & 31) == 0) { ss[w] = s; sq[w] = q; }
    __syncthreads();
    s = 0.f; q = 0.f;
    #pragma unroll
    for (int i = 0; i < 8; i++) { s += ss[i]; q += sq[i]; }
    float mu  = s * (1.0f / DMODEL);
    float var = q * (1.0f / DMODEL) - mu * mu;
    float inv = rsqrtf(var + LN_EPS);
    float4 gv = ((const float4*)gamma)[threadIdx.x];
    float4 bv = ((const float4*)beta)[threadIdx.x];
    float r0 = (v.x - mu) * inv * gv.x + bv.x;
    float r1 = (v.y - mu) * inv * gv.y + bv.y;
    float r2 = (v.z - mu) * inv * gv.z + bv.z;
    float r3 = (v.w - mu) * inv * gv.w + bv.w;
    __nv_bfloat16 h0, h1, h2, h3, l0, l1, l2, l3;
    split1(r0, h0, l0); split1(r1, h1, l1);
    split1(r2, h2, l2); split1(r3, h3, l3);
    size_t o = (size_t)row * DMODEL + threadIdx.x * 4;
    __nv_bfloat162 p;
    p.x = h0; p.y = h1; *(__nv_bfloat162*)(oh + o)     = p;
    p.x = h2; p.y = h3; *(__nv_bfloat162*)(oh + o + 2) = p;
    p.x = l0; p.y = l1; *(__nv_bfloat162*)(ol + o)     = p;
    p.x = l2; p.y = l3; *(__nv_bfloat162*)(ol + o + 2) = p;
}

// ---------------- weight transpose + bf16-split (fused variants) ----------------
__device__ __forceinline__ void tsplit_body(const float* __restrict__ W,
                                            __nv_bfloat16* __restrict__ Th,
                                            __nv_bfloat16* __restrict__ Tl,
                                            int K, int N, int rowOff, int ldT,
                                            float sm[32][33])
{
    int n0 = blockIdx.x * 32, k0 = blockIdx.y * 32;
    int tx = threadIdx.x, ty = threadIdx.y;          // 32 x 8
    #pragma unroll
    for (int j = 0; j < 32; j += 8)
        sm[ty + j][tx] = W[(size_t)(k0 + ty + j) * N + n0 + tx];
    __syncthreads();
    #pragma unroll
    for (int j = 0; j < 32; j += 8) {
        int n = ty + j;
        float v = sm[tx][n];                         // W[k0+tx][n0+n]
        __nv_bfloat16 h, l;
        split1(v, h, l);
        size_t o = (size_t)(rowOff + n0 + n) * ldT + k0 + tx;
        Th[o] = h; Tl[o] = l;
    }
}

// launch 0: W_in + W_out (grid 32 x 32 x 2)
__global__ void tsplit2_kernel(const float* __restrict__ W0, __nv_bfloat16* T0h, __nv_bfloat16* T0l,
                               const float* __restrict__ W1, __nv_bfloat16* T1h, __nv_bfloat16* T1l)
{
    __shared__ float sm[32][33];
    if (blockIdx.z == 0) tsplit_body(W0, T0h, T0l, DMODEL, DMODEL, 0, DMODEL, sm);
    else                 tsplit_body(W1, T1h, T1l, DMODEL, DMODEL, 0, DMODEL, sm);
}

// launch 1: W_so (grid 32 x 4)
__global__ void tsplit_so_kernel(const float* __restrict__ W, __nv_bfloat16* Th, __nv_bfloat16* Tl)
{
    __shared__ float sm[32][33];
    tsplit_body(W, Th, Tl, DSTATE, DMODEL, 0, DSTATE, sm);
}

// launch 2: W_xs / W_B / W_C (grid 4 x 32 x 3)
__global__ void tsplit_cat_kernel(const float* __restrict__ Wxs, const float* __restrict__ WB,
                                  const float* __restrict__ WC,
                                  __nv_bfloat16* Th, __nv_bfloat16* Tl)
{
    __shared__ float sm[32][33];
    const float* W = (blockIdx.z == 0) ? Wxs : (blockIdx.z == 1) ? WB : WC;
    tsplit_body(W, Th, Tl, DMODEL, DSTATE, (int)blockIdx.z * 128, DMODEL, sm);
}

// launch 3: zero-pad WcatT rows [384,512) + build bcat
__global__ void zb_kernel(__nv_bfloat16* __restrict__ Th, __nv_bfloat16* __restrict__ Tl,
                          const float* __restrict__ bB, const float* __restrict__ bC,
                          float* __restrict__ bcat)
{
    int i = blockIdx.x * blockDim.x + threadIdx.x;
    if (i < 128 * DMODEL) {
        __nv_bfloat16 z = __float2bfloat16_rn(0.f);
        Th[(size_t)384 * DMODEL + i] = z;
        Tl[(size_t)384 * DMODEL + i] = z;
    }
    if (i < NCAT) {
        float v = 0.f;
        if (i >= 128 && i < 256) v = bB[i - 128];
        else if (i >= 256 && i < 384) v = bC[i - 256];
        bcat[i] = v;
    }
}

// ---------------- HMMA bf16 3-split GEMM (128x256 tile) ----------------
// C = A @ B^T, A=[M,K] (Ah+Al bf16), B=[N,K] (Bh+Bl bf16, pre-transposed).
// 3-split: C ~= Ah@Bh + Ah@Bl + Al@Bh  (fp32 accumulate)
// Tile: 128x256, BK=64, 256 threads (8 warps 2x4, 64x64 warp tile), double-buffered.
#define HG_BM 128
#define HG_BN 256
#define HG_BK 64
#define HG_OFF_AH 0
#define HG_OFF_AL 16384
#define HG_OFF_BH 32768
#define HG_OFF_BL 65536
#define HG_STAGE  98304
#define HG_SMEM (2 * HG_STAGE + 128)

__device__ __forceinline__ void hg_fill(uint32_t sbase,
                                        const __nv_bfloat16* __restrict__ Ah,
                                        const __nv_bfloat16* __restrict__ Al,
                                        const __nv_bfloat16* __restrict__ Bh,
                                        const __nv_bfloat16* __restrict__ Bl,
                                        int K, int row0, int col0, int k0, int tid)
{
    // A: 128 rows, 2 threads/row (4 chunks each)
    {
        int row = tid >> 1;
        int cb  = (tid & 1) * 4;
        const char* gAh = (const char*)(Ah + (size_t)(row0 + row) * K + k0);
        const char* gAl = (const char*)(Al + (size_t)(row0 + row) * K + k0);
        uint32_t rbase = (uint32_t)row * 128;
        #pragma unroll
        for (int i = 0; i < 4; i++) {
            int c = cb + i;
            uint32_t soff = rbase + (uint32_t)((c ^ (row & 7)) << 4);
            CP_ASYNC16(sbase + HG_OFF_AH + soff, gAh + c * 16);
            CP_ASYNC16(sbase + HG_OFF_AL + soff, gAl + c * 16);
        }
    }
    // B: 256 rows, 1 thread/row (8 chunks each)
    {
        int row = tid;
        const char* gBh = (const char*)(Bh + (size_t)(col0 + row) * K + k0);
        const char* gBl = (const char*)(Bl + (size_t)(col0 + row) * K + k0);
        uint32_t rbase = (uint32_t)row * 128;
        #pragma unroll
        for (int c = 0; c < 8; c++) {
            uint32_t soff = rbase + (uint32_t)((c ^ (row & 7)) << 4);
            CP_ASYNC16(sbase + HG_OFF_BH + soff, gBh + c * 16);
            CP_ASYNC16(sbase + HG_OFF_BL + soff, gBl + c * 16);
        }
    }
}

__global__ __launch_bounds__(256, 1)
void hmma_gemm(const __nv_bfloat16* __restrict__ Ah, const __nv_bfloat16* __restrict__ Al,
               int K,
               const __nv_bfloat16* __restrict__ Bh, const __nv_bfloat16* __restrict__ Bl,
               const float* __restrict__ bias,
               const float* __restrict__ addMat, const float* __restrict__ addScale,
               const float* __restrict__ residual,
               float* __restrict__ Cf,
               __nv_bfloat16* __restrict__ Ch, __nv_bfloat16* __restrict__ Cl,
               int ldc)
{
    extern __shared__ char dsm[];
    uint32_t sbase = (smem_to_u32(dsm) + 127u) & ~127u;

    int tid  = threadIdx.x;
    int lane = tid & 31, warp = tid >> 5;
    int wm = warp >> 2, wn = warp & 3;       // warp tile: 64x64 at (wm*64, wn*64)
    int row0 = blockIdx.y * HG_BM;
    int col0 = blockIdx.x * HG_BN;

    // per-lane ldmatrix geometry
    int r    = lane & 7;
    int tile = lane >> 3;
    int rowA_base = wm * 64 + ((tile & 1) << 3) + r;   // + mt*16
    int kcA       = tile >> 1;
    int rowB_base = wn * 64 + ((tile >> 1) << 3) + r;  // + ng*16
    int kcB       = tile & 1;

    float acc[4][8][4];
    #pragma unroll
    for (int i = 0; i < 4; i++)
        #pragma unroll
        for (int j = 0; j < 8; j++)
            #pragma unroll
            for (int k = 0; k < 4; k++) acc[i][j][k] = 0.f;

    int NS = K / HG_BK;
    hg_fill(sbase, Ah, Al, Bh, Bl, K, row0, col0, 0, tid);
    CP_COMMIT();

    for (int s = 0; s < NS; s++) {
        if (s + 1 < NS) {
            hg_fill(sbase + ((s + 1) & 1) * HG_STAGE, Ah, Al, Bh, Bl, K,
                    row0, col0, (s + 1) * HG_BK, tid);
            CP_COMMIT();
            cp_wait<1>();
        } else {
            cp_wait<0>();
        }
        __syncthreads();

        uint32_t sb = sbase + (s & 1) * HG_STAGE;
        #pragma unroll
        for (int ks = 0; ks < 4; ks++) {
            uint32_t ah[4][4], al[4][4], bh[4][4], bl[4][4];
            uint32_t koA = (uint32_t)((((ks << 1) + kcA) ^ r) << 4);
            uint32_t koB = (uint32_t)((((ks << 1) + kcB) ^ r) << 4);
            #pragma unroll
            for (int mt = 0; mt < 4; mt++) {
                uint32_t rb = (uint32_t)(rowA_base + mt * 16) * 128;
                ldsm4(sb + HG_OFF_AH + rb + koA, ah[mt]);
                ldsm4(sb + HG_OFF_AL + rb + koA, al[mt]);
            }
            #pragma unroll
            for (int ng = 0; ng < 4; ng++) {
                uint32_t rb = (uint32_t)(rowB_base + ng * 16) * 128;
                ldsm4(sb + HG_OFF_BH + rb + koB, bh[ng]);
                ldsm4(sb + HG_OFF_BL + rb + koB, bl[ng]);
            }
            #pragma unroll
            for (int mt = 0; mt < 4; mt++) {
                #pragma unroll
                for (int nt = 0; nt < 8; nt++) {
                    const uint32_t* bhp = &bh[nt >> 1][(nt & 1) * 2];
                    const uint32_t* blp = &bl[nt >> 1][(nt & 1) * 2];
                    mma16816(acc[mt][nt], ah[mt], bhp);
                    mma16816(acc[mt][nt], ah[mt], blp);
                    mma16816(acc[mt][nt], al[mt], bhp);
                }
            }
        }
        __syncthreads();
    }

    // ---------- epilogue ----------
    int mbase = row0 + wm * 64 + (lane >> 2);
    int nbase = col0 + wn * 64 + ((lane & 3) << 1);
    #pragma unroll
    for (int mt = 0; mt < 4; mt++) {
        #pragma unroll
        for (int nt = 0; nt < 8; nt++) {
            int n = nbase + nt * 8;
            float b0 = 0.f, b1 = 0.f;
            if (bias) { b0 = bias[n]; b1 = bias[n + 1]; }
            #pragma unroll
            for (int h2 = 0; h2 < 2; h2++) {
                int m = mbase + mt * 16 + h2 * 8;
                size_t off = (size_t)m * ldc + n;
                float v0 = acc[mt][nt][h2 * 2 + 0] + b0;
                float v1 = acc[mt][nt][h2 * 2 + 1] + b1;
                if (addMat) {
                    float2 mm = *(const float2*)(addMat + off);
                    v0 += addScale[n]     * mm.x;
                    v1 += addScale[n + 1] * mm.y;
                }
                if (residual) {
                    float2 rr = *(const float2*)(residual + off);
                    v0 += rr.x; v1 += rr.y;
                }
                if (Cf) { float2 o; o.x = v0; o.y = v1; *(float2*)(Cf + off) = o; }
                if (Ch) {
                    __nv_bfloat16 h0, h1, l0, l1;
                    split1(v0, h0, l0); split1(v1, h1, l1);
                    __nv_bfloat162 p;
                    p.x = h0; p.y = h1; *(__nv_bfloat162*)(Ch + off) = p;
                    p.x = l0; p.y = l1; *(__nv_bfloat162*)(Cl + off) = p;
                }
            }
        }
    }
}

// ---------------- chunked linear scan: y[t] = r*y[t-1] + xs[t]*B[t] ----------------
__global__ void scan1_kernel(const float* __restrict__ zcat, const float* __restrict__ A_log,
                             float* __restrict__ yloc, float* __restrict__ carry)
{
    int b = blockIdx.x / NCHUNK;
    int c = blockIdx.x % NCHUNK;
    int s = threadIdx.x;                             // 0..127
    float r = expf(-expf(A_log[s]));
    size_t row = (size_t)b * LSEQ + (size_t)c * CHUNK;
    const float* zp = zcat + row * NCAT;
    float* yp = yloc + row * DSTATE;
    float acc = 0.f;
    #pragma unroll 4
    for (int i = 0; i < CHUNK; i++) {
        float xs = zp[(size_t)i * NCAT + s];
        float bb = zp[(size_t)i * NCAT + 128 + s];
        acc = acc * r + xs * bb;
        yp[i * DSTATE + s] = acc;
    }
    carry[((size_t)b * NCHUNK + c) * DSTATE + s] = acc;
}

// compute chunk prefix from carries locally, inject, multiply by C_sel, emit ys split
__global__ void scan3_kernel(const float* __restrict__ yloc, const float* __restrict__ carry,
                             const float* __restrict__ zcat, const float* __restrict__ A_log,
                             __nv_bfloat16* __restrict__ ysh, __nv_bfloat16* __restrict__ ysl)
{
    int b = blockIdx.x / NCHUNK;
    int c = blockIdx.x % NCHUNK;
    int s = threadIdx.x;
    float a  = -expf(A_log[s]);
    float r  = expf(a);
    float rC = expf(a * (float)CHUNK);
    float st = 0.f;
    for (int j = 0; j < c; j++)
        st = st * rC + carry[((size_t)b * NCHUNK + j) * DSTATE + s];
    float p = st;
    size_t row = (size_t)b * LSEQ + (size_t)c * CHUNK;
    const float* yp = yloc + row * DSTATE;
    const float* cp = zcat + row * NCAT + 256;       // C_sel columns
    size_t obase = row * DSTATE;
    #pragma unroll 4
    for (int i = 0; i < CHUNK; i++) {
        p *= r;
        float v = (yp[i * DSTATE + s] + p) * cp[(size_t)i * NCAT + s];
        __nv_bfloat16 h, l;
        split1(v, h, l);
        ysh[obase + i * DSTATE + s] = h;
        ysl[obase + i * DSTATE + s] = l;
    }
}

// ---------------- host ----------------
static float* sym_addr_f(const void* symbol)
{
    void* p = nullptr;
    cudaGetSymbolAddress(&p, symbol);
    return (float*)p;
}
static __nv_bfloat16* sym_addr_b(const void* symbol)
{
    void* p = nullptr;
    cudaGetSymbolAddress(&p, symbol);
    return (__nv_bfloat16*)p;
}

extern "C" void kernel_launch(void* const* d_in, const int* in_sizes, int n_in,
                              void* d_out, int out_size)
{
    (void)in_sizes; (void)n_in; (void)out_size;
    const float* x      = (const float*)d_in[0];
    const float* ln_g   = (const float*)d_in[1];
    const float* ln_b   = (const float*)d_in[2];
    const float* W_in   = (const float*)d_in[3];
    const float* b_in   = (const float*)d_in[4];
    const float* W_xs   = (const float*)d_in[5];
    const float* W_B    = (const float*)d_in[6];
    const float* b_B    = (const float*)d_in[7];
    const float* W_C    = (const float*)d_in[8];
    const float* b_C    = (const float*)d_in[9];
    const float* A_log  = (const float*)d_in[10];
    const float* Dvec   = (const float*)d_in[11];
    const float* W_so   = (const float*)d_in[12];
    const float* W_out  = (const float*)d_in[13];
    const float* b_out  = (const float*)d_in[14];
    float* out = (float*)d_out;

    float* z    = sym_addr_f(g_z);
    float* zcat = sym_addr_f(g_zcat);
    float* yloc = sym_addr_f(g_yloc);
    float* carry = sym_addr_f(g_carry);
    float* bcat  = sym_addr_f(g_bcat);
    __nv_bfloat16* xnh = sym_addr_b(g_xnh);
    __nv_bfloat16* xnl = sym_addr_b(g_xnl);
    __nv_bfloat16* zh  = sym_addr_b(g_zh);
    __nv_bfloat16* zl  = sym_addr_b(g_zl);
    __nv_bfloat16* yh  = sym_addr_b(g_yh);
    __nv_bfloat16* yl  = sym_addr_b(g_yl);
    __nv_bfloat16* ysh = sym_addr_b(g_ysh);
    __nv_bfloat16* ysl = sym_addr_b(g_ysl);
    __nv_bfloat16* WinT_h  = sym_addr_b(g_WinT_h);
    __nv_bfloat16* WinT_l  = sym_addr_b(g_WinT_l);
    __nv_bfloat16* WoutT_h = sym_addr_b(g_WoutT_h);
    __nv_bfloat16* WoutT_l = sym_addr_b(g_WoutT_l);
    __nv_bfloat16* WsoT_h  = sym_addr_b(g_WsoT_h);
    __nv_bfloat16* WsoT_l  = sym_addr_b(g_WsoT_l);
    __nv_bfloat16* WcatT_h = sym_addr_b(g_WcatT_h);
    __nv_bfloat16* WcatT_l = sym_addr_b(g_WcatT_l);

    cudaFuncSetAttribute(hmma_gemm, cudaFuncAttributeMaxDynamicSharedMemorySize, HG_SMEM);

    dim3 tsb(32, 8);
    // launches 0-3: weight prep
    tsplit2_kernel<<<dim3(32, 32, 2), tsb>>>(W_in, WinT_h, WinT_l, W_out, WoutT_h, WoutT_l);
    tsplit_so_kernel<<<dim3(32, 4), tsb>>>(W_so, WsoT_h, WsoT_l);
    tsplit_cat_kernel<<<dim3(4, 32, 3), tsb>>>(W_xs, W_B, W_C, WcatT_h, WcatT_l);
    zb_kernel<<<(128 * DMODEL + 255) / 256, 256>>>(WcatT_h, WcatT_l, b_B, b_C, bcat);

    // launch 4: LayerNorm -> xn (bf16 split)
    ln_kernel<<<MROWS, 256>>>(x, ln_g, ln_b, xnh, xnl);

    // launch 5 (ncu -s 5 -c 1 profiles this): z = xn @ W_in + b_in
    hmma_gemm<<<dim3(DMODEL / HG_BN, MROWS / HG_BM), 256, HG_SMEM>>>(
        xnh, xnl, DMODEL, WinT_h, WinT_l, b_in,
        nullptr, nullptr, nullptr, z, zh, zl, DMODEL);

    // fused projections: zcat = z @ [W_xs | W_B | W_C | 0] + bcat  (fp32)
    hmma_gemm<<<dim3(NCAT / HG_BN, MROWS / HG_BM), 256, HG_SMEM>>>(
        zh, zl, DMODEL, WcatT_h, WcatT_l, bcat,
        nullptr, nullptr, nullptr, zcat, nullptr, nullptr, NCAT);

    // chunked linear scan (u = xs*Bsel fused in scan1; prefix + *C_sel + split in scan3)
    scan1_kernel<<<NBATCH * NCHUNK, DSTATE>>>(zcat, A_log, yloc, carry);
    scan3_kernel<<<NBATCH * NCHUNK, DSTATE>>>(yloc, carry, zcat, A_log, ysh, ysl);

    // y = ys @ W_so + D * z   (bf16 split y only)
    hmma_gemm<<<dim3(DMODEL / HG_BN, MROWS / HG_BM), 256, HG_SMEM>>>(
        ysh, ysl, DSTATE, WsoT_h, WsoT_l, nullptr,
        z, Dvec, nullptr, nullptr, yh, yl, DMODEL);

    // out = y @ W_out + b_out + x
    hmma_gemm<<<dim3(DMODEL / HG_BN, MROWS / HG_BM), 256, HG_SMEM>>>(
        yh, yl, DMODEL, WoutT_h, WoutT_l, b_out,
        nullptr, nullptr, x, out, nullptr, nullptr, DMODEL);
}

// round 10
// speedup vs baseline: 1.2983x; 1.2983x over previous
#include <cuda_runtime.h>
#include <cuda_bf16.h>
#include <math.h>
#include <stdint.h>

// ---------------- problem constants ----------------
#define DMODEL 1024
#define DSTATE 128
#define LSEQ   4096
#define NBATCH 4
#define MROWS  (NBATCH * LSEQ)   // 16384
#define LN_EPS 1e-3f

#define CHUNK  64
#define NCHUNK (LSEQ / CHUNK)    // 64
#define NCAT   512               // padded 3*128 fused projection width

// ---------------- portable PTX helpers (sm_80+ features only) ----------------
__device__ __forceinline__ uint32_t smem_to_u32(const void* smem_ptr) {
    uint32_t addr;
    asm("{ .reg .u64 tmp; cvta.to.shared.u64 tmp, %1; cvt.u32.u64 %0, tmp; }"
        : "=r"(addr) : "l"(smem_ptr));
    return addr;
}

#define CP_ASYNC16(smem_u32, gptr) \
    asm volatile("cp.async.cg.shared.global [%0], [%1], 16;" \
        :: "r"(smem_u32), "l"(gptr) : "memory")
#define CP_COMMIT() asm volatile("cp.async.commit_group;" ::: "memory")

template <int N>
__device__ __forceinline__ void cp_wait() {
    asm volatile("cp.async.wait_group %0;" :: "n"(N) : "memory");
}

__device__ __forceinline__ void ldsm4(uint32_t addr, uint32_t* r) {
    asm volatile("ldmatrix.sync.aligned.m8n8.x4.shared.b16 {%0,%1,%2,%3}, [%4];"
        : "=r"(r[0]), "=r"(r[1]), "=r"(r[2]), "=r"(r[3]) : "r"(addr));
}

__device__ __forceinline__ void mma16816(float* c, const uint32_t* a, const uint32_t* b) {
    asm volatile(
        "mma.sync.aligned.m16n8k16.row.col.f32.bf16.bf16.f32 "
        "{%0,%1,%2,%3}, {%4,%5,%6,%7}, {%8,%9}, {%0,%1,%2,%3};"
        : "+f"(c[0]), "+f"(c[1]), "+f"(c[2]), "+f"(c[3])
        : "r"(a[0]), "r"(a[1]), "r"(a[2]), "r"(a[3]), "r"(b[0]), "r"(b[1]));
}

__device__ __forceinline__ void split1(float v, __nv_bfloat16& h, __nv_bfloat16& l) {
    h = __float2bfloat16_rn(v);
    l = __float2bfloat16_rn(v - __bfloat162float(h));
}

// ---------------- scratch (static device globals; no allocation) ----------------
__device__ float g_z   [(size_t)MROWS * DMODEL];
__device__ float g_zcat[(size_t)MROWS * NCAT];
__device__ float g_yloc[(size_t)MROWS * DSTATE];
__device__ float g_carry[NBATCH * NCHUNK * DSTATE];
// bf16-split activations
__device__ __nv_bfloat16 g_xnh[(size_t)MROWS * DMODEL];
__device__ __nv_bfloat16 g_xnl[(size_t)MROWS * DMODEL];
__device__ __nv_bfloat16 g_zh [(size_t)MROWS * DMODEL];
__device__ __nv_bfloat16 g_zl [(size_t)MROWS * DMODEL];
__device__ __nv_bfloat16 g_yh [(size_t)MROWS * DMODEL];
__device__ __nv_bfloat16 g_yl [(size_t)MROWS * DMODEL];
__device__ __nv_bfloat16 g_ysh[(size_t)MROWS * DSTATE];
__device__ __nv_bfloat16 g_ysl[(size_t)MROWS * DSTATE];
// pre-transposed, bf16-split weights ([N, K] layout, K-major)
__device__ __nv_bfloat16 g_WinT_h [(size_t)DMODEL * DMODEL];
__device__ __nv_bfloat16 g_WinT_l [(size_t)DMODEL * DMODEL];
__device__ __nv_bfloat16 g_WoutT_h[(size_t)DMODEL * DMODEL];
__device__ __nv_bfloat16 g_WoutT_l[(size_t)DMODEL * DMODEL];
__device__ __nv_bfloat16 g_WsoT_h [(size_t)DMODEL * DSTATE];
__device__ __nv_bfloat16 g_WsoT_l [(size_t)DMODEL * DSTATE];
__device__ __nv_bfloat16 g_WcatT_h[(size_t)NCAT * DMODEL];
__device__ __nv_bfloat16 g_WcatT_l[(size_t)NCAT * DMODEL];
__device__ float g_bcat[NCAT];

// ---------------- LayerNorm (emits bf16 h/l split directly) ----------------
__global__ void ln_kernel(const float* __restrict__ x,
                          const float* __restrict__ gamma,
                          const float* __restrict__ beta,
                          __nv_bfloat16* __restrict__ oh,
                          __nv_bfloat16* __restrict__ ol)
{
    int row = blockIdx.x;
    const float4* xr = (const float4*)(x + (size_t)row * DMODEL);
    float4 v = xr[threadIdx.x];
    float s = v.x + v.y + v.z + v.w;
    float q = v.x * v.x + v.y * v.y + v.z * v.z + v.w * v.w;
    #pragma unroll
    for (int o = 16; o; o >>= 1) {
        s += __shfl_xor_sync(0xffffffffu, s, o);
        q += __shfl_xor_sync(0xffffffffu, q, o);
    }
    __shared__ float ss[8], sq[8];
    int w = threadIdx.x >> 5;
    if ((threadIdx.x & 31) == 0) { ss[w] = s; sq[w] = q; }
    __syncthreads();
    s = 0.f; q = 0.f;
    #pragma unroll
    for (int i = 0; i < 8; i++) { s += ss[i]; q += sq[i]; }
    float mu  = s * (1.0f / DMODEL);
    float var = q * (1.0f / DMODEL) - mu * mu;
    float inv = rsqrtf(var + LN_EPS);
    float4 gv = ((const float4*)gamma)[threadIdx.x];
    float4 bv = ((const float4*)beta)[threadIdx.x];
    float r0 = (v.x - mu) * inv * gv.x + bv.x;
    float r1 = (v.y - mu) * inv * gv.y + bv.y;
    float r2 = (v.z - mu) * inv * gv.z + bv.z;
    float r3 = (v.w - mu) * inv * gv.w + bv.w;
    __nv_bfloat16 h0, h1, h2, h3, l0, l1, l2, l3;
    split1(r0, h0, l0); split1(r1, h1, l1);
    split1(r2, h2, l2); split1(r3, h3, l3);
    size_t o = (size_t)row * DMODEL + threadIdx.x * 4;
    __nv_bfloat162 p;
    p.x = h0; p.y = h1; *(__nv_bfloat162*)(oh + o)     = p;
    p.x = h2; p.y = h3; *(__nv_bfloat162*)(oh + o + 2) = p;
    p.x = l0; p.y = l1; *(__nv_bfloat162*)(ol + o)     = p;
    p.x = l2; p.y = l3; *(__nv_bfloat162*)(ol + o + 2) = p;
}

// ---------------- weight transpose + bf16-split (fused variants) ----------------
__device__ __forceinline__ void tsplit_body(const float* __restrict__ W,
                                            __nv_bfloat16* __restrict__ Th,
                                            __nv_bfloat16* __restrict__ Tl,
                                            int K, int N, int rowOff, int ldT,
                                            float sm[32][33])
{
    int n0 = blockIdx.x * 32, k0 = blockIdx.y * 32;
    int tx = threadIdx.x, ty = threadIdx.y;          // 32 x 8
    #pragma unroll
    for (int j = 0; j < 32; j += 8)
        sm[ty + j][tx] = W[(size_t)(k0 + ty + j) * N + n0 + tx];
    __syncthreads();
    #pragma unroll
    for (int j = 0; j < 32; j += 8) {
        int n = ty + j;
        float v = sm[tx][n];                         // W[k0+tx][n0+n]
        __nv_bfloat16 h, l;
        split1(v, h, l);
        size_t o = (size_t)(rowOff + n0 + n) * ldT + k0 + tx;
        Th[o] = h; Tl[o] = l;
    }
}

__global__ void tsplit2_kernel(const float* __restrict__ W0, __nv_bfloat16* T0h, __nv_bfloat16* T0l,
                               const float* __restrict__ W1, __nv_bfloat16* T1h, __nv_bfloat16* T1l)
{
    __shared__ float sm[32][33];
    if (blockIdx.z == 0) tsplit_body(W0, T0h, T0l, DMODEL, DMODEL, 0, DMODEL, sm);
    else                 tsplit_body(W1, T1h, T1l, DMODEL, DMODEL, 0, DMODEL, sm);
}

__global__ void tsplit_so_kernel(const float* __restrict__ W, __nv_bfloat16* Th, __nv_bfloat16* Tl)
{
    __shared__ float sm[32][33];
    tsplit_body(W, Th, Tl, DSTATE, DMODEL, 0, DSTATE, sm);
}

__global__ void tsplit_cat_kernel(const float* __restrict__ Wxs, const float* __restrict__ WB,
                                  const float* __restrict__ WC,
                                  __nv_bfloat16* Th, __nv_bfloat16* Tl)
{
    __shared__ float sm[32][33];
    const float* W = (blockIdx.z == 0) ? Wxs : (blockIdx.z == 1) ? WB : WC;
    tsplit_body(W, Th, Tl, DMODEL, DSTATE, (int)blockIdx.z * 128, DMODEL, sm);
}

__global__ void zb_kernel(__nv_bfloat16* __restrict__ Th, __nv_bfloat16* __restrict__ Tl,
                          const float* __restrict__ bB, const float* __restrict__ bC,
                          float* __restrict__ bcat)
{
    int i = blockIdx.x * blockDim.x + threadIdx.x;
    if (i < 128 * DMODEL) {
        __nv_bfloat16 z = __float2bfloat16_rn(0.f);
        Th[(size_t)384 * DMODEL + i] = z;
        Tl[(size_t)384 * DMODEL + i] = z;
    }
    if (i < NCAT) {
        float v = 0.f;
        if (i >= 128 && i < 256) v = bB[i - 128];
        else if (i >= 256 && i < 384) v = bC[i - 256];
        bcat[i] = v;
    }
}

// ---------------- HMMA bf16 3-split GEMM (128x128 tile, BK=32, 3 stages, occ 2) ----------------
// C = A @ B^T, A=[M,K] (Ah+Al bf16), B=[N,K] (Bh+Bl bf16, pre-transposed).
// 3-split: C ~= Ah@Bh + Ah@Bl + Al@Bh  (fp32 accumulate)
// 256 threads, 8 warps (2x4), 64x32 warp tile. 64B rows, swizzle: chunk ^= (row>>1)&3.
#define HG_BM 128
#define HG_BN 128
#define HG_BK 32
#define HG_OFF_AH 0
#define HG_OFF_AL 8192
#define HG_OFF_BH 16384
#define HG_OFF_BL 24576
#define HG_STAGE  32768
#define HG_NSTAGE 3
#define HG_SMEM (HG_NSTAGE * HG_STAGE + 128)

__global__ __launch_bounds__(256, 2)
void hmma_gemm(const __nv_bfloat16* __restrict__ Ah, const __nv_bfloat16* __restrict__ Al,
               int K,
               const __nv_bfloat16* __restrict__ Bh, const __nv_bfloat16* __restrict__ Bl,
               const float* __restrict__ bias,
               const float* __restrict__ addMat, const float* __restrict__ addScale,
               const float* __restrict__ residual,
               float* __restrict__ Cf,
               __nv_bfloat16* __restrict__ Ch, __nv_bfloat16* __restrict__ Cl,
               int ldc)
{
    extern __shared__ char dsm[];
    uint32_t sbase = (smem_to_u32(dsm) + 127u) & ~127u;

    int tid  = threadIdx.x;
    int lane = tid & 31, warp = tid >> 5;
    int wm = warp >> 2, wn = warp & 3;       // warp tile: 64x32 at (wm*64, wn*32)
    int row0 = blockIdx.y * HG_BM;
    int col0 = blockIdx.x * HG_BN;

    // ---- fill geometry (precomputed per thread) ----
    int frow = tid >> 1;                     // 0..127
    int fcb  = (tid & 1) * 2;                // chunk base 0 or 2
    uint32_t fsw = (uint32_t)((frow >> 1) & 3);
    uint32_t fs0 = (uint32_t)frow * 64 + (((uint32_t)fcb       ^ fsw) << 4);
    uint32_t fs1 = (uint32_t)frow * 64 + (((uint32_t)(fcb + 1) ^ fsw) << 4);
    const char* pAh = (const char*)(Ah + (size_t)(row0 + frow) * K) + fcb * 16;
    const char* pAl = (const char*)(Al + (size_t)(row0 + frow) * K) + fcb * 16;
    const char* pBh = (const char*)(Bh + (size_t)(col0 + frow) * K) + fcb * 16;
    const char* pBl = (const char*)(Bl + (size_t)(col0 + frow) * K) + fcb * 16;

    // ---- ldmatrix geometry ----
    int r    = lane & 7;
    int tile = lane >> 3;
    int rowA_base = wm * 64 + ((tile & 1) << 3) + r;   // + mt*16
    int kcA       = tile >> 1;                          // 0 or 1
    int rowB_base = wn * 32 + ((tile >> 1) << 3) + r;  // + ng*16
    int kcB       = tile & 1;
    uint32_t swA = (uint32_t)((rowA_base >> 1) & 3);   // mt*16 doesn't change bits [1:2]
    uint32_t swB = (uint32_t)((rowB_base >> 1) & 3);

    float acc[4][4][4];
    #pragma unroll
    for (int i = 0; i < 4; i++)
        #pragma unroll
        for (int j = 0; j < 4; j++)
            #pragma unroll
            for (int k = 0; k < 4; k++) acc[i][j][k] = 0.f;

    int NS = K / HG_BK;                      // >= 4 for all our GEMMs

    // prologue: fill stages 0, 1
    #pragma unroll
    for (int p = 0; p < 2; p++) {
        uint32_t sb = sbase + p * HG_STAGE;
        size_t gk = (size_t)p * HG_BK * 2;   // byte offset along K
        CP_ASYNC16(sb + HG_OFF_AH + fs0, pAh + gk);
        CP_ASYNC16(sb + HG_OFF_AH + fs1, pAh + gk + 16);
        CP_ASYNC16(sb + HG_OFF_AL + fs0, pAl + gk);
        CP_ASYNC16(sb + HG_OFF_AL + fs1, pAl + gk + 16);
        CP_ASYNC16(sb + HG_OFF_BH + fs0, pBh + gk);
        CP_ASYNC16(sb + HG_OFF_BH + fs1, pBh + gk + 16);
        CP_ASYNC16(sb + HG_OFF_BL + fs0, pBl + gk);
        CP_ASYNC16(sb + HG_OFF_BL + fs1, pBl + gk + 16);
        CP_COMMIT();
    }

    int buf = 0, fbuf = 2;
    for (int s = 0; s < NS; s++) {
        if (s + 2 < NS) {
            uint32_t sb = sbase + fbuf * HG_STAGE;
            size_t gk = (size_t)(s + 2) * HG_BK * 2;
            CP_ASYNC16(sb + HG_OFF_AH + fs0, pAh + gk);
            CP_ASYNC16(sb + HG_OFF_AH + fs1, pAh + gk + 16);
            CP_ASYNC16(sb + HG_OFF_AL + fs0, pAl + gk);
            CP_ASYNC16(sb + HG_OFF_AL + fs1, pAl + gk + 16);
            CP_ASYNC16(sb + HG_OFF_BH + fs0, pBh + gk);
            CP_ASYNC16(sb + HG_OFF_BH + fs1, pBh + gk + 16);
            CP_ASYNC16(sb + HG_OFF_BL + fs0, pBl + gk);
            CP_ASYNC16(sb + HG_OFF_BL + fs1, pBl + gk + 16);
            CP_COMMIT();
            cp_wait<2>();
        } else if (s + 1 < NS) {
            cp_wait<1>();
        } else {
            cp_wait<0>();
        }
        __syncthreads();

        uint32_t sb = sbase + buf * HG_STAGE;
        #pragma unroll
        for (int ks = 0; ks < 2; ks++) {
            uint32_t ah[4][4], al[4][4], bh[2][4], bl[2][4];
            uint32_t koA = ((((uint32_t)(ks * 2 + kcA)) ^ swA) << 4);
            uint32_t koB = ((((uint32_t)(ks * 2 + kcB)) ^ swB) << 4);
            #pragma unroll
            for (int mt = 0; mt < 4; mt++) {
                uint32_t rb = (uint32_t)(rowA_base + mt * 16) * 64;
                ldsm4(sb + HG_OFF_AH + rb + koA, ah[mt]);
                ldsm4(sb + HG_OFF_AL + rb + koA, al[mt]);
            }
            #pragma unroll
            for (int ng = 0; ng < 2; ng++) {
                uint32_t rb = (uint32_t)(rowB_base + ng * 16) * 64;
                ldsm4(sb + HG_OFF_BH + rb + koB, bh[ng]);
                ldsm4(sb + HG_OFF_BL + rb + koB, bl[ng]);
            }
            #pragma unroll
            for (int mt = 0; mt < 4; mt++) {
                #pragma unroll
                for (int nt = 0; nt < 4; nt++) {
                    const uint32_t* bhp = &bh[nt >> 1][(nt & 1) * 2];
                    const uint32_t* blp = &bl[nt >> 1][(nt & 1) * 2];
                    mma16816(acc[mt][nt], ah[mt], bhp);
                    mma16816(acc[mt][nt], ah[mt], blp);
                    mma16816(acc[mt][nt], al[mt], bhp);
                }
            }
        }
        __syncthreads();
        buf  = (buf == 2)  ? 0 : buf + 1;
        fbuf = (fbuf == 2) ? 0 : fbuf + 1;
    }

    // ---------- epilogue ----------
    int mbase = row0 + wm * 64 + (lane >> 2);
    int nbase = col0 + wn * 32 + ((lane & 3) << 1);
    #pragma unroll
    for (int mt = 0; mt < 4; mt++) {
        #pragma unroll
        for (int nt = 0; nt < 4; nt++) {
            int n = nbase + nt * 8;
            float b0 = 0.f, b1 = 0.f;
            if (bias) { b0 = bias[n]; b1 = bias[n + 1]; }
            #pragma unroll
            for (int h2 = 0; h2 < 2; h2++) {
                int m = mbase + mt * 16 + h2 * 8;
                size_t off = (size_t)m * ldc + n;
                float v0 = acc[mt][nt][h2 * 2 + 0] + b0;
                float v1 = acc[mt][nt][h2 * 2 + 1] + b1;
                if (addMat) {
                    float2 mm = *(const float2*)(addMat + off);
                    v0 += addScale[n]     * mm.x;
                    v1 += addScale[n + 1] * mm.y;
                }
                if (residual) {
                    float2 rr = *(const float2*)(residual + off);
                    v0 += rr.x; v1 += rr.y;
                }
                if (Cf) { float2 o; o.x = v0; o.y = v1; *(float2*)(Cf + off) = o; }
                if (Ch) {
                    __nv_bfloat16 h0, h1, l0, l1;
                    split1(v0, h0, l0); split1(v1, h1, l1);
                    __nv_bfloat162 p;
                    p.x = h0; p.y = h1; *(__nv_bfloat162*)(Ch + off) = p;
                    p.x = l0; p.y = l1; *(__nv_bfloat162*)(Cl + off) = p;
                }
            }
        }
    }
}

// ---------------- chunked linear scan: y[t] = r*y[t-1] + xs[t]*B[t] ----------------
__global__ void scan1_kernel(const float* __restrict__ zcat, const float* __restrict__ A_log,
                             float* __restrict__ yloc, float* __restrict__ carry)
{
    int b = blockIdx.x / NCHUNK;
    int c = blockIdx.x % NCHUNK;
    int s = threadIdx.x;                             // 0..127
    float r = expf(-expf(A_log[s]));
    size_t row = (size_t)b * LSEQ + (size_t)c * CHUNK;
    const float* zp = zcat + row * NCAT;
    float* yp = yloc + row * DSTATE;
    float acc = 0.f;
    #pragma unroll 4
    for (int i = 0; i < CHUNK; i++) {
        float xs = zp[(size_t)i * NCAT + s];
        float bb = zp[(size_t)i * NCAT + 128 + s];
        acc = acc * r + xs * bb;
        yp[i * DSTATE + s] = acc;
    }
    carry[((size_t)b * NCHUNK + c) * DSTATE + s] = acc;
}

// compute chunk prefix from carries locally, inject, multiply by C_sel, emit ys split
__global__ void scan3_kernel(const float* __restrict__ yloc, const float* __restrict__ carry,
                             const float* __restrict__ zcat, const float* __restrict__ A_log,
                             __nv_bfloat16* __restrict__ ysh, __nv_bfloat16* __restrict__ ysl)
{
    int b = blockIdx.x / NCHUNK;
    int c = blockIdx.x % NCHUNK;
    int s = threadIdx.x;
    float a  = -expf(A_log[s]);
    float r  = expf(a);
    float rC = expf(a * (float)CHUNK);
    float st = 0.f;
    for (int j = 0; j < c; j++)
        st = st * rC + carry[((size_t)b * NCHUNK + j) * DSTATE + s];
    float p = st;
    size_t row = (size_t)b * LSEQ + (size_t)c * CHUNK;
    const float* yp = yloc + row * DSTATE;
    const float* cp = zcat + row * NCAT + 256;       // C_sel columns
    size_t obase = row * DSTATE;
    #pragma unroll 4
    for (int i = 0; i < CHUNK; i++) {
        p *= r;
        float v = (yp[i * DSTATE + s] + p) * cp[(size_t)i * NCAT + s];
        __nv_bfloat16 h, l;
        split1(v, h, l);
        ysh[obase + i * DSTATE + s] = h;
        ysl[obase + i * DSTATE + s] = l;
    }
}

// ---------------- host ----------------
static float* sym_addr_f(const void* symbol)
{
    void* p = nullptr;
    cudaGetSymbolAddress(&p, symbol);
    return (float*)p;
}
static __nv_bfloat16* sym_addr_b(const void* symbol)
{
    void* p = nullptr;
    cudaGetSymbolAddress(&p, symbol);
    return (__nv_bfloat16*)p;
}

extern "C" void kernel_launch(void* const* d_in, const int* in_sizes, int n_in,
                              void* d_out, int out_size)
{
    (void)in_sizes; (void)n_in; (void)out_size;
    const float* x      = (const float*)d_in[0];
    const float* ln_g   = (const float*)d_in[1];
    const float* ln_b   = (const float*)d_in[2];
    const float* W_in   = (const float*)d_in[3];
    const float* b_in   = (const float*)d_in[4];
    const float* W_xs   = (const float*)d_in[5];
    const float* W_B    = (const float*)d_in[6];
    const float* b_B    = (const float*)d_in[7];
    const float* W_C    = (const float*)d_in[8];
    const float* b_C    = (const float*)d_in[9];
    const float* A_log  = (const float*)d_in[10];
    const float* Dvec   = (const float*)d_in[11];
    const float* W_so   = (const float*)d_in[12];
    const float* W_out  = (const float*)d_in[13];
    const float* b_out  = (const float*)d_in[14];
    float* out = (float*)d_out;

    float* z    = sym_addr_f(g_z);
    float* zcat = sym_addr_f(g_zcat);
    float* yloc = sym_addr_f(g_yloc);
    float* carry = sym_addr_f(g_carry);
    float* bcat  = sym_addr_f(g_bcat);
    __nv_bfloat16* xnh = sym_addr_b(g_xnh);
    __nv_bfloat16* xnl = sym_addr_b(g_xnl);
    __nv_bfloat16* zh  = sym_addr_b(g_zh);
    __nv_bfloat16* zl  = sym_addr_b(g_zl);
    __nv_bfloat16* yh  = sym_addr_b(g_yh);
    __nv_bfloat16* yl  = sym_addr_b(g_yl);
    __nv_bfloat16* ysh = sym_addr_b(g_ysh);
    __nv_bfloat16* ysl = sym_addr_b(g_ysl);
    __nv_bfloat16* WinT_h  = sym_addr_b(g_WinT_h);
    __nv_bfloat16* WinT_l  = sym_addr_b(g_WinT_l);
    __nv_bfloat16* WoutT_h = sym_addr_b(g_WoutT_h);
    __nv_bfloat16* WoutT_l = sym_addr_b(g_WoutT_l);
    __nv_bfloat16* WsoT_h  = sym_addr_b(g_WsoT_h);
    __nv_bfloat16* WsoT_l  = sym_addr_b(g_WsoT_l);
    __nv_bfloat16* WcatT_h = sym_addr_b(g_WcatT_h);
    __nv_bfloat16* WcatT_l = sym_addr_b(g_WcatT_l);

    cudaFuncSetAttribute(hmma_gemm, cudaFuncAttributeMaxDynamicSharedMemorySize, HG_SMEM);

    dim3 tsb(32, 8);
    // weight prep
    tsplit2_kernel<<<dim3(32, 32, 2), tsb>>>(W_in, WinT_h, WinT_l, W_out, WoutT_h, WoutT_l);
    tsplit_so_kernel<<<dim3(32, 4), tsb>>>(W_so, WsoT_h, WsoT_l);
    tsplit_cat_kernel<<<dim3(4, 32, 3), tsb>>>(W_xs, W_B, W_C, WcatT_h, WcatT_l);
    zb_kernel<<<(128 * DMODEL + 255) / 256, 256>>>(WcatT_h, WcatT_l, b_B, b_C, bcat);

    // LayerNorm -> xn (bf16 split)
    ln_kernel<<<MROWS, 256>>>(x, ln_g, ln_b, xnh, xnl);

    // z = xn @ W_in + b_in   (fp32 z for D-skip, bf16 split z for next GEMMs)
    hmma_gemm<<<dim3(DMODEL / HG_BN, MROWS / HG_BM), 256, HG_SMEM>>>(
        xnh, xnl, DMODEL, WinT_h, WinT_l, b_in,
        nullptr, nullptr, nullptr, z, zh, zl, DMODEL);

    // fused projections: zcat = z @ [W_xs | W_B | W_C | 0] + bcat  (fp32)
    hmma_gemm<<<dim3(NCAT / HG_BN, MROWS / HG_BM), 256, HG_SMEM>>>(
        zh, zl, DMODEL, WcatT_h, WcatT_l, bcat,
        nullptr, nullptr, nullptr, zcat, nullptr, nullptr, NCAT);

    // chunked linear scan (u = xs*Bsel fused in scan1; prefix + *C_sel + split in scan3)
    scan1_kernel<<<NBATCH * NCHUNK, DSTATE>>>(zcat, A_log, yloc, carry);
    scan3_kernel<<<NBATCH * NCHUNK, DSTATE>>>(yloc, carry, zcat, A_log, ysh, ysl);

    // y = ys @ W_so + D * z   (bf16 split y only)
    hmma_gemm<<<dim3(DMODEL / HG_BN, MROWS / HG_BM), 256, HG_SMEM>>>(
        ysh, ysl, DSTATE, WsoT_h, WsoT_l, nullptr,
        z, Dvec, nullptr, nullptr, yh, yl, DMODEL);

    // out = y @ W_out + b_out + x
    hmma_gemm<<<dim3(DMODEL / HG_BN, MROWS / HG_BM), 256, HG_SMEM>>>(
        yh, yl, DMODEL, WoutT_h, WoutT_l, b_out,
        nullptr, nullptr, x, out, nullptr, nullptr, DMODEL);
}

// round 11
// speedup vs baseline: 1.3434x; 1.0347x over previous
#include <cuda_runtime.h>
#include <cuda_bf16.h>
#include <math.h>
#include <stdint.h>

// ---------------- problem constants ----------------
#define DMODEL 1024
#define DSTATE 128
#define LSEQ   4096
#define NBATCH 4
#define MROWS  (NBATCH * LSEQ)   // 16384
#define LN_EPS 1e-3f

#define CHUNK  64
#define NCHUNK (LSEQ / CHUNK)    // 64
#define NCAT   512               // padded 3*128 fused projection width

// ---------------- portable PTX helpers (sm_80+ features only) ----------------
__device__ __forceinline__ uint32_t smem_to_u32(const void* smem_ptr) {
    uint32_t addr;
    asm("{ .reg .u64 tmp; cvta.to.shared.u64 tmp, %1; cvt.u32.u64 %0, tmp; }"
        : "=r"(addr) : "l"(smem_ptr));
    return addr;
}

#define CP_ASYNC16(smem_u32, gptr) \
    asm volatile("cp.async.cg.shared.global [%0], [%1], 16;" \
        :: "r"(smem_u32), "l"(gptr) : "memory")
#define CP_COMMIT() asm volatile("cp.async.commit_group;" ::: "memory")

template <int N>
__device__ __forceinline__ void cp_wait() {
    asm volatile("cp.async.wait_group %0;" :: "n"(N) : "memory");
}

__device__ __forceinline__ void ldsm4(uint32_t addr, uint32_t* r) {
    asm volatile("ldmatrix.sync.aligned.m8n8.x4.shared.b16 {%0,%1,%2,%3}, [%4];"
        : "=r"(r[0]), "=r"(r[1]), "=r"(r[2]), "=r"(r[3]) : "r"(addr));
}

__device__ __forceinline__ void mma16816(float* c, const uint32_t* a, const uint32_t* b) {
    asm volatile(
        "mma.sync.aligned.m16n8k16.row.col.f32.bf16.bf16.f32 "
        "{%0,%1,%2,%3}, {%4,%5,%6,%7}, {%8,%9}, {%0,%1,%2,%3};"
        : "+f"(c[0]), "+f"(c[1]), "+f"(c[2]), "+f"(c[3])
        : "r"(a[0]), "r"(a[1]), "r"(a[2]), "r"(a[3]), "r"(b[0]), "r"(b[1]));
}

__device__ __forceinline__ void split1(float v, __nv_bfloat16& h, __nv_bfloat16& l) {
    h = __float2bfloat16_rn(v);
    l = __float2bfloat16_rn(v - __bfloat162float(h));
}

// ---------------- scratch (static device globals; no allocation) ----------------
__device__ float g_z   [(size_t)MROWS * DMODEL];
__device__ float g_zcat[(size_t)MROWS * NCAT];
__device__ float g_yloc[(size_t)MROWS * DSTATE];
__device__ float g_carry[NBATCH * NCHUNK * DSTATE];
// bf16-split activations
__device__ __nv_bfloat16 g_xnh[(size_t)MROWS * DMODEL];
__device__ __nv_bfloat16 g_xnl[(size_t)MROWS * DMODEL];
__device__ __nv_bfloat16 g_zh [(size_t)MROWS * DMODEL];
__device__ __nv_bfloat16 g_zl [(size_t)MROWS * DMODEL];
__device__ __nv_bfloat16 g_yh [(size_t)MROWS * DMODEL];
__device__ __nv_bfloat16 g_yl [(size_t)MROWS * DMODEL];
__device__ __nv_bfloat16 g_ysh[(size_t)MROWS * DSTATE];
__device__ __nv_bfloat16 g_ysl[(size_t)MROWS * DSTATE];
// pre-transposed, bf16-split weights ([N, K] layout, K-major)
__device__ __nv_bfloat16 g_WinT_h [(size_t)DMODEL * DMODEL];
__device__ __nv_bfloat16 g_WinT_l [(size_t)DMODEL * DMODEL];
__device__ __nv_bfloat16 g_WoutT_h[(size_t)DMODEL * DMODEL];
__device__ __nv_bfloat16 g_WoutT_l[(size_t)DMODEL * DMODEL];
__device__ __nv_bfloat16 g_WsoT_h [(size_t)DMODEL * DSTATE];
__device__ __nv_bfloat16 g_WsoT_l [(size_t)DMODEL * DSTATE];
__device__ __nv_bfloat16 g_WcatT_h[(size_t)NCAT * DMODEL];
__device__ __nv_bfloat16 g_WcatT_l[(size_t)NCAT * DMODEL];
__device__ float g_bcat[NCAT];

// ---------------- LayerNorm (emits bf16 h/l split directly) ----------------
__global__ void ln_kernel(const float* __restrict__ x,
                          const float* __restrict__ gamma,
                          const float* __restrict__ beta,
                          __nv_bfloat16* __restrict__ oh,
                          __nv_bfloat16* __restrict__ ol)
{
    int row = blockIdx.x;
    const float4* xr = (const float4*)(x + (size_t)row * DMODEL);
    float4 v = xr[threadIdx.x];
    float s = v.x + v.y + v.z + v.w;
    float q = v.x * v.x + v.y * v.y + v.z * v.z + v.w * v.w;
    #pragma unroll
    for (int o = 16; o; o >>= 1) {
        s += __shfl_xor_sync(0xffffffffu, s, o);
        q += __shfl_xor_sync(0xffffffffu, q, o);
    }
    __shared__ float ss[8], sq[8];
    int w = threadIdx.x >> 5;
    if ((threadIdx.x & 31) == 0) { ss[w] = s; sq[w] = q; }
    __syncthreads();
    s = 0.f; q = 0.f;
    #pragma unroll
    for (int i = 0; i < 8; i++) { s += ss[i]; q += sq[i]; }
    float mu  = s * (1.0f / DMODEL);
    float var = q * (1.0f / DMODEL) - mu * mu;
    float inv = rsqrtf(var + LN_EPS);
    float4 gv = ((const float4*)gamma)[threadIdx.x];
    float4 bv = ((const float4*)beta)[threadIdx.x];
    float r0 = (v.x - mu) * inv * gv.x + bv.x;
    float r1 = (v.y - mu) * inv * gv.y + bv.y;
    float r2 = (v.z - mu) * inv * gv.z + bv.z;
    float r3 = (v.w - mu) * inv * gv.w + bv.w;
    __nv_bfloat16 h0, h1, h2, h3, l0, l1, l2, l3;
    split1(r0, h0, l0); split1(r1, h1, l1);
    split1(r2, h2, l2); split1(r3, h3, l3);
    size_t o = (size_t)row * DMODEL + threadIdx.x * 4;
    __nv_bfloat162 p;
    p.x = h0; p.y = h1; *(__nv_bfloat162*)(oh + o)     = p;
    p.x = h2; p.y = h3; *(__nv_bfloat162*)(oh + o + 2) = p;
    p.x = l0; p.y = l1; *(__nv_bfloat162*)(ol + o)     = p;
    p.x = l2; p.y = l3; *(__nv_bfloat162*)(ol + o + 2) = p;
}

// ---------------- fused weight prep: transpose + bf16-split + pad + bcat ----------------
__device__ __forceinline__ void tsplit_body(const float* __restrict__ W,
                                            __nv_bfloat16* __restrict__ Th,
                                            __nv_bfloat16* __restrict__ Tl,
                                            int N, int rowOff, int ldT,
                                            int n0, int k0, float sm[32][33])
{
    int tx = threadIdx.x, ty = threadIdx.y;          // 32 x 8
    #pragma unroll
    for (int j = 0; j < 32; j += 8)
        sm[ty + j][tx] = W[(size_t)(k0 + ty + j) * N + n0 + tx];
    __syncthreads();
    #pragma unroll
    for (int j = 0; j < 32; j += 8) {
        int n = ty + j;
        float v = sm[tx][n];                         // W[k0+tx][n0+n]
        __nv_bfloat16 h, l;
        split1(v, h, l);
        size_t o = (size_t)(rowOff + n0 + n) * ldT + k0 + tx;
        Th[o] = h; Tl[o] = l;
    }
}

// grid (32, 32, 3), block (32, 8)
__global__ void prep_kernel(const float* __restrict__ W_in,  const float* __restrict__ W_out,
                            const float* __restrict__ W_so,
                            const float* __restrict__ W_xs,  const float* __restrict__ W_B,
                            const float* __restrict__ W_C,
                            const float* __restrict__ bB,    const float* __restrict__ bC,
                            __nv_bfloat16* WinT_h,  __nv_bfloat16* WinT_l,
                            __nv_bfloat16* WoutT_h, __nv_bfloat16* WoutT_l,
                            __nv_bfloat16* WsoT_h,  __nv_bfloat16* WsoT_l,
                            __nv_bfloat16* WcatT_h, __nv_bfloat16* WcatT_l,
                            float* __restrict__ bcat)
{
    __shared__ float sm[32][33];
    int z = blockIdx.z;
    if (z == 0) {
        tsplit_body(W_in, WinT_h, WinT_l, DMODEL, 0, DMODEL,
                    (int)blockIdx.x * 32, (int)blockIdx.y * 32, sm);
    } else if (z == 1) {
        tsplit_body(W_out, WoutT_h, WoutT_l, DMODEL, 0, DMODEL,
                    (int)blockIdx.x * 32, (int)blockIdx.y * 32, sm);
    } else {
        int idx = (int)blockIdx.x + 32 * (int)blockIdx.y;    // 0..1023
        if (idx < 128) {
            // W_so: [K=128, N=1024] -> T[1024,128]; 32 n-blocks x 4 k-blocks
            int bx = idx & 31, by = idx >> 5;
            tsplit_body(W_so, WsoT_h, WsoT_l, DMODEL, 0, DSTATE, bx * 32, by * 32, sm);
        } else if (idx < 512) {
            // W_xs/W_B/W_C: [K=1024, N=128] -> rows of WcatT; 4 n-blocks x 32 k-blocks each
            int j = idx - 128;                   // 0..383
            int w = j >> 7;                      // 0..2
            int rr = j & 127;
            int bx = rr & 3, by = rr >> 2;
            const float* W = (w == 0) ? W_xs : (w == 1) ? W_B : W_C;
            tsplit_body(W, WcatT_h, WcatT_l, DSTATE, w * 128, DMODEL, bx * 32, by * 32, sm);
        } else {
            // zero-pad WcatT rows [384,512) + build bcat
            int i = (idx - 512) * 256 + (int)threadIdx.y * 32 + (int)threadIdx.x;
            __nv_bfloat16 zv = __float2bfloat16_rn(0.f);
            WcatT_h[(size_t)384 * DMODEL + i] = zv;
            WcatT_l[(size_t)384 * DMODEL + i] = zv;
            if (i < NCAT) {
                float v = 0.f;
                if (i >= 128 && i < 256) v = bB[i - 128];
                else if (i >= 256 && i < 384) v = bC[i - 256];
                bcat[i] = v;
            }
        }
    }
}

// ---------------- HMMA bf16 3-split GEMM (128x128 tile, BK=32, 3 stages, occ 2) ----------------
// C = A @ B^T, A=[M,K] (Ah+Al bf16), B=[N,K] (Bh+Bl bf16, pre-transposed).
// 3-split: C ~= Ah@Bh + Ah@Bl + Al@Bh  (fp32 accumulate)
// 256 threads, 8 warps (2x4), 64x32 warp tile. 64B rows, swizzle: chunk ^= (row>>1)&3.
// Single __syncthreads per K-stage: wait -> sync -> fill(s+2) -> compute(s).
#define HG_BM 128
#define HG_BN 128
#define HG_BK 32
#define HG_OFF_AH 0
#define HG_OFF_AL 8192
#define HG_OFF_BH 16384
#define HG_OFF_BL 24576
#define HG_STAGE  32768
#define HG_NSTAGE 3
#define HG_SMEM (HG_NSTAGE * HG_STAGE + 128)

__global__ __launch_bounds__(256, 2)
void hmma_gemm(const __nv_bfloat16* __restrict__ Ah, const __nv_bfloat16* __restrict__ Al,
               int K,
               const __nv_bfloat16* __restrict__ Bh, const __nv_bfloat16* __restrict__ Bl,
               const float* __restrict__ bias,
               const float* __restrict__ addMat, const float* __restrict__ addScale,
               const float* __restrict__ residual,
               float* __restrict__ Cf,
               __nv_bfloat16* __restrict__ Ch, __nv_bfloat16* __restrict__ Cl,
               int ldc)
{
    extern __shared__ char dsm[];
    uint32_t sbase = (smem_to_u32(dsm) + 127u) & ~127u;

    int tid  = threadIdx.x;
    int lane = tid & 31, warp = tid >> 5;
    int wm = warp >> 2, wn = warp & 3;       // warp tile: 64x32 at (wm*64, wn*32)
    int row0 = blockIdx.y * HG_BM;
    int col0 = blockIdx.x * HG_BN;

    // ---- fill geometry (precomputed per thread) ----
    int frow = tid >> 1;                     // 0..127
    int fcb  = (tid & 1) * 2;                // chunk base 0 or 2
    uint32_t fsw = (uint32_t)((frow >> 1) & 3);
    uint32_t fs0 = (uint32_t)frow * 64 + (((uint32_t)fcb       ^ fsw) << 4);
    uint32_t fs1 = (uint32_t)frow * 64 + (((uint32_t)(fcb + 1) ^ fsw) << 4);
    const char* pAh = (const char*)(Ah + (size_t)(row0 + frow) * K) + fcb * 16;
    const char* pAl = (const char*)(Al + (size_t)(row0 + frow) * K) + fcb * 16;
    const char* pBh = (const char*)(Bh + (size_t)(col0 + frow) * K) + fcb * 16;
    const char* pBl = (const char*)(Bl + (size_t)(col0 + frow) * K) + fcb * 16;

    // ---- ldmatrix geometry ----
    int r    = lane & 7;
    int tile = lane >> 3;
    int rowA_base = wm * 64 + ((tile & 1) << 3) + r;   // + mt*16
    int kcA       = tile >> 1;                          // 0 or 1
    int rowB_base = wn * 32 + ((tile >> 1) << 3) + r;  // + ng*16
    int kcB       = tile & 1;
    uint32_t swA = (uint32_t)((rowA_base >> 1) & 3);   // mt*16 doesn't change bits [1:2]
    uint32_t swB = (uint32_t)((rowB_base >> 1) & 3);

    float acc[4][4][4];
    #pragma unroll
    for (int i = 0; i < 4; i++)
        #pragma unroll
        for (int j = 0; j < 4; j++)
            #pragma unroll
            for (int k = 0; k < 4; k++) acc[i][j][k] = 0.f;

    int NS = K / HG_BK;                      // >= 4 for all our GEMMs

    // prologue: fill stages 0, 1
    #pragma unroll
    for (int p = 0; p < 2; p++) {
        uint32_t sb = sbase + p * HG_STAGE;
        size_t gk = (size_t)p * HG_BK * 2;   // byte offset along K
        CP_ASYNC16(sb + HG_OFF_AH + fs0, pAh + gk);
        CP_ASYNC16(sb + HG_OFF_AH + fs1, pAh + gk + 16);
        CP_ASYNC16(sb + HG_OFF_AL + fs0, pAl + gk);
        CP_ASYNC16(sb + HG_OFF_AL + fs1, pAl + gk + 16);
        CP_ASYNC16(sb + HG_OFF_BH + fs0, pBh + gk);
        CP_ASYNC16(sb + HG_OFF_BH + fs1, pBh + gk + 16);
        CP_ASYNC16(sb + HG_OFF_BL + fs0, pBl + gk);
        CP_ASYNC16(sb + HG_OFF_BL + fs1, pBl + gk + 16);
        CP_COMMIT();
    }

    int buf = 0, fbuf = 2;
    for (int s = 0; s < NS; s++) {
        // stage s's fill is the oldest pending group (at most 2 in flight)
        if (s + 1 < NS) cp_wait<1>(); else cp_wait<0>();
        __syncthreads();

        // fill stage s+2 into fbuf = (s+2)%3 == (s-1)%3; its last readers
        // finished at iteration s-1, strictly before this barrier. Safe.
        if (s + 2 < NS) {
            uint32_t sb = sbase + fbuf * HG_STAGE;
            size_t gk = (size_t)(s + 2) * HG_BK * 2;
            CP_ASYNC16(sb + HG_OFF_AH + fs0, pAh + gk);
            CP_ASYNC16(sb + HG_OFF_AH + fs1, pAh + gk + 16);
            CP_ASYNC16(sb + HG_OFF_AL + fs0, pAl + gk);
            CP_ASYNC16(sb + HG_OFF_AL + fs1, pAl + gk + 16);
            CP_ASYNC16(sb + HG_OFF_BH + fs0, pBh + gk);
            CP_ASYNC16(sb + HG_OFF_BH + fs1, pBh + gk + 16);
            CP_ASYNC16(sb + HG_OFF_BL + fs0, pBl + gk);
            CP_ASYNC16(sb + HG_OFF_BL + fs1, pBl + gk + 16);
            CP_COMMIT();
        }

        uint32_t sb = sbase + buf * HG_STAGE;
        #pragma unroll
        for (int ks = 0; ks < 2; ks++) {
            uint32_t ah[4][4], al[4][4], bh[2][4], bl[2][4];
            uint32_t koA = ((((uint32_t)(ks * 2 + kcA)) ^ swA) << 4);
            uint32_t koB = ((((uint32_t)(ks * 2 + kcB)) ^ swB) << 4);
            #pragma unroll
            for (int mt = 0; mt < 4; mt++) {
                uint32_t rb = (uint32_t)(rowA_base + mt * 16) * 64;
                ldsm4(sb + HG_OFF_AH + rb + koA, ah[mt]);
                ldsm4(sb + HG_OFF_AL + rb + koA, al[mt]);
            }
            #pragma unroll
            for (int ng = 0; ng < 2; ng++) {
                uint32_t rb = (uint32_t)(rowB_base + ng * 16) * 64;
                ldsm4(sb + HG_OFF_BH + rb + koB, bh[ng]);
                ldsm4(sb + HG_OFF_BL + rb + koB, bl[ng]);
            }
            #pragma unroll
            for (int mt = 0; mt < 4; mt++) {
                #pragma unroll
                for (int nt = 0; nt < 4; nt++) {
                    const uint32_t* bhp = &bh[nt >> 1][(nt & 1) * 2];
                    const uint32_t* blp = &bl[nt >> 1][(nt & 1) * 2];
                    mma16816(acc[mt][nt], ah[mt], bhp);
                    mma16816(acc[mt][nt], ah[mt], blp);
                    mma16816(acc[mt][nt], al[mt], bhp);
                }
            }
        }
        buf  = (buf == 2)  ? 0 : buf + 1;
        fbuf = (fbuf == 2) ? 0 : fbuf + 1;
    }

    // ---------- epilogue ----------
    int mbase = row0 + wm * 64 + (lane >> 2);
    int nbase = col0 + wn * 32 + ((lane & 3) << 1);
    #pragma unroll
    for (int mt = 0; mt < 4; mt++) {
        #pragma unroll
        for (int nt = 0; nt < 4; nt++) {
            int n = nbase + nt * 8;
            float b0 = 0.f, b1 = 0.f;
            if (bias) { b0 = bias[n]; b1 = bias[n + 1]; }
            #pragma unroll
            for (int h2 = 0; h2 < 2; h2++) {
                int m = mbase + mt * 16 + h2 * 8;
                size_t off = (size_t)m * ldc + n;
                float v0 = acc[mt][nt][h2 * 2 + 0] + b0;
                float v1 = acc[mt][nt][h2 * 2 + 1] + b1;
                if (addMat) {
                    float2 mm = *(const float2*)(addMat + off);
                    v0 += addScale[n]     * mm.x;
                    v1 += addScale[n + 1] * mm.y;
                }
                if (residual) {
                    float2 rr = *(const float2*)(residual + off);
                    v0 += rr.x; v1 += rr.y;
                }
                if (Cf) { float2 o; o.x = v0; o.y = v1; *(float2*)(Cf + off) = o; }
                if (Ch) {
                    __nv_bfloat16 h0, h1, l0, l1;
                    split1(v0, h0, l0); split1(v1, h1, l1);
                    __nv_bfloat162 p;
                    p.x = h0; p.y = h1; *(__nv_bfloat162*)(Ch + off) = p;
                    p.x = l0; p.y = l1; *(__nv_bfloat162*)(Cl + off) = p;
                }
            }
        }
    }
}

// ---------------- chunked linear scan: y[t] = r*y[t-1] + xs[t]*B[t] ----------------
__global__ void scan1_kernel(const float* __restrict__ zcat, const float* __restrict__ A_log,
                             float* __restrict__ yloc, float* __restrict__ carry)
{
    int b = blockIdx.x / NCHUNK;
    int c = blockIdx.x % NCHUNK;
    int s = threadIdx.x;                             // 0..127
    float r = expf(-expf(A_log[s]));
    size_t row = (size_t)b * LSEQ + (size_t)c * CHUNK;
    const float* zp = zcat + row * NCAT;
    float* yp = yloc + row * DSTATE;
    float acc = 0.f;
    #pragma unroll 4
    for (int i = 0; i < CHUNK; i++) {
        float xs = zp[(size_t)i * NCAT + s];
        float bb = zp[(size_t)i * NCAT + 128 + s];
        acc = acc * r + xs * bb;
        yp[i * DSTATE + s] = acc;
    }
    carry[((size_t)b * NCHUNK + c) * DSTATE + s] = acc;
}

// compute chunk prefix from carries locally, inject, multiply by C_sel, emit ys split
__global__ void scan3_kernel(const float* __restrict__ yloc, const float* __restrict__ carry,
                             const float* __restrict__ zcat, const float* __restrict__ A_log,
                             __nv_bfloat16* __restrict__ ysh, __nv_bfloat16* __restrict__ ysl)
{
    int b = blockIdx.x / NCHUNK;
    int c = blockIdx.x % NCHUNK;
    int s = threadIdx.x;
    float a  = -expf(A_log[s]);
    float r  = expf(a);
    float rC = expf(a * (float)CHUNK);
    float st = 0.f;
    for (int j = 0; j < c; j++)
        st = st * rC + carry[((size_t)b * NCHUNK + j) * DSTATE + s];
    float p = st;
    size_t row = (size_t)b * LSEQ + (size_t)c * CHUNK;
    const float* yp = yloc + row * DSTATE;
    const float* cp = zcat + row * NCAT + 256;       // C_sel columns
    size_t obase = row * DSTATE;
    #pragma unroll 4
    for (int i = 0; i < CHUNK; i++) {
        p *= r;
        float v = (yp[i * DSTATE + s] + p) * cp[(size_t)i * NCAT + s];
        __nv_bfloat16 h, l;
        split1(v, h, l);
        ysh[obase + i * DSTATE + s] = h;
        ysl[obase + i * DSTATE + s] = l;
    }
}

// ---------------- host ----------------
static float* sym_addr_f(const void* symbol)
{
    void* p = nullptr;
    cudaGetSymbolAddress(&p, symbol);
    return (float*)p;
}
static __nv_bfloat16* sym_addr_b(const void* symbol)
{
    void* p = nullptr;
    cudaGetSymbolAddress(&p, symbol);
    return (__nv_bfloat16*)p;
}

extern "C" void kernel_launch(void* const* d_in, const int* in_sizes, int n_in,
                              void* d_out, int out_size)
{
    (void)in_sizes; (void)n_in; (void)out_size;
    const float* x      = (const float*)d_in[0];
    const float* ln_g   = (const float*)d_in[1];
    const float* ln_b   = (const float*)d_in[2];
    const float* W_in   = (const float*)d_in[3];
    const float* b_in   = (const float*)d_in[4];
    const float* W_xs   = (const float*)d_in[5];
    const float* W_B    = (const float*)d_in[6];
    const float* b_B    = (const float*)d_in[7];
    const float* W_C    = (const float*)d_in[8];
    const float* b_C    = (const float*)d_in[9];
    const float* A_log  = (const float*)d_in[10];
    const float* Dvec   = (const float*)d_in[11];
    const float* W_so   = (const float*)d_in[12];
    const float* W_out  = (const float*)d_in[13];
    const float* b_out  = (const float*)d_in[14];
    float* out = (float*)d_out;

    float* z    = sym_addr_f(g_z);
    float* zcat = sym_addr_f(g_zcat);
    float* yloc = sym_addr_f(g_yloc);
    float* carry = sym_addr_f(g_carry);
    float* bcat  = sym_addr_f(g_bcat);
    __nv_bfloat16* xnh = sym_addr_b(g_xnh);
    __nv_bfloat16* xnl = sym_addr_b(g_xnl);
    __nv_bfloat16* zh  = sym_addr_b(g_zh);
    __nv_bfloat16* zl  = sym_addr_b(g_zl);
    __nv_bfloat16* yh  = sym_addr_b(g_yh);
    __nv_bfloat16* yl  = sym_addr_b(g_yl);
    __nv_bfloat16* ysh = sym_addr_b(g_ysh);
    __nv_bfloat16* ysl = sym_addr_b(g_ysl);
    __nv_bfloat16* WinT_h  = sym_addr_b(g_WinT_h);
    __nv_bfloat16* WinT_l  = sym_addr_b(g_WinT_l);
    __nv_bfloat16* WoutT_h = sym_addr_b(g_WoutT_h);
    __nv_bfloat16* WoutT_l = sym_addr_b(g_WoutT_l);
    __nv_bfloat16* WsoT_h  = sym_addr_b(g_WsoT_h);
    __nv_bfloat16* WsoT_l  = sym_addr_b(g_WsoT_l);
    __nv_bfloat16* WcatT_h = sym_addr_b(g_WcatT_h);
    __nv_bfloat16* WcatT_l = sym_addr_b(g_WcatT_l);

    cudaFuncSetAttribute(hmma_gemm, cudaFuncAttributeMaxDynamicSharedMemorySize, HG_SMEM);

    // fused weight prep (1 launch)
    prep_kernel<<<dim3(32, 32, 3), dim3(32, 8)>>>(
        W_in, W_out, W_so, W_xs, W_B, W_C, b_B, b_C,
        WinT_h, WinT_l, WoutT_h, WoutT_l, WsoT_h, WsoT_l, WcatT_h, WcatT_l, bcat);

    // LayerNorm -> xn (bf16 split)
    ln_kernel<<<MROWS, 256>>>(x, ln_g, ln_b, xnh, xnl);

    // z = xn @ W_in + b_in   (fp32 z for D-skip, bf16 split z for next GEMMs)
    hmma_gemm<<<dim3(DMODEL / HG_BN, MROWS / HG_BM), 256, HG_SMEM>>>(
        xnh, xnl, DMODEL, WinT_h, WinT_l, b_in,
        nullptr, nullptr, nullptr, z, zh, zl, DMODEL);

    // fused projections: zcat = z @ [W_xs | W_B | W_C | 0] + bcat  (fp32)
    hmma_gemm<<<dim3(NCAT / HG_BN, MROWS / HG_BM), 256, HG_SMEM>>>(
        zh, zl, DMODEL, WcatT_h, WcatT_l, bcat,
        nullptr, nullptr, nullptr, zcat, nullptr, nullptr, NCAT);

    // chunked linear scan (u = xs*Bsel fused in scan1; prefix + *C_sel + split in scan3)
    scan1_kernel<<<NBATCH * NCHUNK, DSTATE>>>(zcat, A_log, yloc, carry);
    scan3_kernel<<<NBATCH * NCHUNK, DSTATE>>>(yloc, carry, zcat, A_log, ysh, ysl);

    // y = ys @ W_so + D * z   (bf16 split y only)
    hmma_gemm<<<dim3(DMODEL / HG_BN, MROWS / HG_BM), 256, HG_SMEM>>>(
        ysh, ysl, DSTATE, WsoT_h, WsoT_l, nullptr,
        z, Dvec, nullptr, nullptr, yh, yl, DMODEL);

    // out = y @ W_out + b_out + x
    hmma_gemm<<<dim3(DMODEL / HG_BN, MROWS / HG_BM), 256, HG_SMEM>>>(
        yh, yl, DMODEL, WoutT_h, WoutT_l, b_out,
        nullptr, nullptr, x, out, nullptr, nullptr, DMODEL);
}

// round 13
// speedup vs baseline: 1.9190x; 1.4285x over previous
#include <cuda_runtime.h>
#include <cuda_fp16.h>
#include <math.h>
#include <stdint.h>

// ---------------- problem constants ----------------
#define DMODEL 1024
#define DSTATE 128
#define LSEQ   4096
#define NBATCH 4
#define MROWS  (NBATCH * LSEQ)   // 16384
#define LN_EPS 1e-3f

#define CHUNK  64
#define NCHUNK (LSEQ / CHUNK)    // 64
#define NCAT   512               // padded 3*128 fused projection width

// ---------------- portable PTX helpers (sm_80+ features only) ----------------
__device__ __forceinline__ uint32_t smem_to_u32(const void* smem_ptr) {
    uint32_t addr;
    asm("{ .reg .u64 tmp; cvta.to.shared.u64 tmp, %1; cvt.u32.u64 %0, tmp; }"
        : "=r"(addr) : "l"(smem_ptr));
    return addr;
}

#define CP_ASYNC16(smem_u32, gptr) \
    asm volatile("cp.async.cg.shared.global [%0], [%1], 16;" \
        :: "r"(smem_u32), "l"(gptr) : "memory")
#define CP_COMMIT() asm volatile("cp.async.commit_group;" ::: "memory")

template <int N>
__device__ __forceinline__ void cp_wait() {
    asm volatile("cp.async.wait_group %0;" :: "n"(N) : "memory");
}

__device__ __forceinline__ void ldsm4(uint32_t addr, uint32_t* r) {
    asm volatile("ldmatrix.sync.aligned.m8n8.x4.shared.b16 {%0,%1,%2,%3}, [%4];"
        : "=r"(r[0]), "=r"(r[1]), "=r"(r[2]), "=r"(r[3]) : "r"(addr));
}

// fp16 inputs, fp32 accumulate
__device__ __forceinline__ void mma16816(float* c, const uint32_t* a, const uint32_t* b) {
    asm volatile(
        "mma.sync.aligned.m16n8k16.row.col.f32.f16.f16.f32 "
        "{%0,%1,%2,%3}, {%4,%5,%6,%7}, {%8,%9}, {%0,%1,%2,%3};"
        : "+f"(c[0]), "+f"(c[1]), "+f"(c[2]), "+f"(c[3])
        : "r"(a[0]), "r"(a[1]), "r"(a[2]), "r"(a[3]), "r"(b[0]), "r"(b[1]));
}

// fp16 2-term split: h captures 11 bits, l the next 11 -> ~22-bit weight precision
__device__ __forceinline__ void split1h(float v, __half& h, __half& l) {
    h = __float2half_rn(v);
    l = __float2half_rn(v - __half2float(h));
}

// ---------------- scratch (static device globals; no allocation) ----------------
__device__ float g_z   [(size_t)MROWS * DMODEL];
__device__ float g_zcat[(size_t)MROWS * NCAT];
__device__ float g_yloc[(size_t)MROWS * DSTATE];
__device__ float g_carry[NBATCH * NCHUNK * DSTATE];
// fp16 activations (single copy)
__device__ __half g_xnf[(size_t)MROWS * DMODEL];
__device__ __half g_zf [(size_t)MROWS * DMODEL];
__device__ __half g_yf [(size_t)MROWS * DMODEL];
__device__ __half g_ysf[(size_t)MROWS * DSTATE];
// pre-transposed, fp16-split weights ([N, K] layout, K-major)
__device__ __half g_WinT_h [(size_t)DMODEL * DMODEL];
__device__ __half g_WinT_l [(size_t)DMODEL * DMODEL];
__device__ __half g_WoutT_h[(size_t)DMODEL * DMODEL];
__device__ __half g_WoutT_l[(size_t)DMODEL * DMODEL];
__device__ __half g_WsoT_h [(size_t)DMODEL * DSTATE];
__device__ __half g_WsoT_l [(size_t)DMODEL * DSTATE];
__device__ __half g_WcatT_h[(size_t)NCAT * DMODEL];
__device__ __half g_WcatT_l[(size_t)NCAT * DMODEL];
__device__ float g_bcat[NCAT];

// ---------------- LayerNorm (emits fp16 directly) ----------------
__global__ void ln_kernel(const float* __restrict__ x,
                          const float* __restrict__ gamma,
                          const float* __restrict__ beta,
                          __half* __restrict__ of)
{
    int row = blockIdx.x;
    const float4* xr = (const float4*)(x + (size_t)row * DMODEL);
    float4 v = xr[threadIdx.x];
    float s = v.x + v.y + v.z + v.w;
    float q = v.x * v.x + v.y * v.y + v.z * v.z + v.w * v.w;
    #pragma unroll
    for (int o = 16; o; o >>= 1) {
        s += __shfl_xor_sync(0xffffffffu, s, o);
        q += __shfl_xor_sync(0xffffffffu, q, o);
    }
    __shared__ float ss[8], sq[8];
    int w = threadIdx.x >> 5;
    if ((threadIdx.x & 31) == 0) { ss[w] = s; sq[w] = q; }
    __syncthreads();
    s = 0.f; q = 0.f;
    #pragma unroll
    for (int i = 0; i < 8; i++) { s += ss[i]; q += sq[i]; }
    float mu  = s * (1.0f / DMODEL);
    float var = q * (1.0f / DMODEL) - mu * mu;
    float inv = rsqrtf(var + LN_EPS);
    float4 gv = ((const float4*)gamma)[threadIdx.x];
    float4 bv = ((const float4*)beta)[threadIdx.x];
    float r0 = (v.x - mu) * inv * gv.x + bv.x;
    float r1 = (v.y - mu) * inv * gv.y + bv.y;
    float r2 = (v.z - mu) * inv * gv.z + bv.z;
    float r3 = (v.w - mu) * inv * gv.w + bv.w;
    size_t o = (size_t)row * DMODEL + threadIdx.x * 4;
    __half2 p;
    p.x = __float2half_rn(r0); p.y = __float2half_rn(r1);
    *(__half2*)(of + o) = p;
    p.x = __float2half_rn(r2); p.y = __float2half_rn(r3);
    *(__half2*)(of + o + 2) = p;
}

// ---------------- fused weight prep: transpose + fp16-split + pad + bcat ----------------
__device__ __forceinline__ void tsplit_body(const float* __restrict__ W,
                                            __half* __restrict__ Th,
                                            __half* __restrict__ Tl,
                                            int N, int rowOff, int ldT,
                                            int n0, int k0, float sm[32][33])
{
    int tx = threadIdx.x, ty = threadIdx.y;          // 32 x 8
    #pragma unroll
    for (int j = 0; j < 32; j += 8)
        sm[ty + j][tx] = W[(size_t)(k0 + ty + j) * N + n0 + tx];
    __syncthreads();
    #pragma unroll
    for (int j = 0; j < 32; j += 8) {
        int n = ty + j;
        float v = sm[tx][n];                         // W[k0+tx][n0+n]
        __half h, l;
        split1h(v, h, l);
        size_t o = (size_t)(rowOff + n0 + n) * ldT + k0 + tx;
        Th[o] = h; Tl[o] = l;
    }
}

// grid (32, 32, 3), block (32, 8)
__global__ void prep_kernel(const float* __restrict__ W_in,  const float* __restrict__ W_out,
                            const float* __restrict__ W_so,
                            const float* __restrict__ W_xs,  const float* __restrict__ W_B,
                            const float* __restrict__ W_C,
                            const float* __restrict__ bB,    const float* __restrict__ bC,
                            __half* WinT_h,  __half* WinT_l,
                            __half* WoutT_h, __half* WoutT_l,
                            __half* WsoT_h,  __half* WsoT_l,
                            __half* WcatT_h, __half* WcatT_l,
                            float* __restrict__ bcat)
{
    __shared__ float sm[32][33];
    int z = blockIdx.z;
    if (z == 0) {
        tsplit_body(W_in, WinT_h, WinT_l, DMODEL, 0, DMODEL,
                    (int)blockIdx.x * 32, (int)blockIdx.y * 32, sm);
    } else if (z == 1) {
        tsplit_body(W_out, WoutT_h, WoutT_l, DMODEL, 0, DMODEL,
                    (int)blockIdx.x * 32, (int)blockIdx.y * 32, sm);
    } else {
        int idx = (int)blockIdx.x + 32 * (int)blockIdx.y;    // 0..1023
        if (idx < 128) {
            int bx = idx & 31, by = idx >> 5;
            tsplit_body(W_so, WsoT_h, WsoT_l, DMODEL, 0, DSTATE, bx * 32, by * 32, sm);
        } else if (idx < 512) {
            int j = idx - 128;                   // 0..383
            int w = j >> 7;                      // 0..2
            int rr = j & 127;
            int bx = rr & 3, by = rr >> 2;
            const float* W = (w == 0) ? W_xs : (w == 1) ? W_B : W_C;
            tsplit_body(W, WcatT_h, WcatT_l, DSTATE, w * 128, DMODEL, bx * 32, by * 32, sm);
        } else {
            int i = (idx - 512) * 256 + (int)threadIdx.y * 32 + (int)threadIdx.x;
            __half zv = __float2half_rn(0.f);
            WcatT_h[(size_t)384 * DMODEL + i] = zv;
            WcatT_l[(size_t)384 * DMODEL + i] = zv;
            if (i < NCAT) {
                float v = 0.f;
                if (i >= 128 && i < 256) v = bB[i - 128];
                else if (i >= 256 && i < 384) v = bC[i - 256];
                bcat[i] = v;
            }
        }
    }
}

// ---------------- HMMA fp16 weight-split GEMM (128x128 tile, BK=32, 4 stages, occ 2) ----------------
// C = A @ B^T, A=[M,K] single fp16, B=[N,K] fp16 2-split (Bh+Bl, pre-transposed).
// C = A@Bh + A@Bl  (fp32 accumulate): 2 MMAs per fragment pair.
// 256 threads, 8 warps (2x4), 64x32 warp tile. 64B rows, swizzle: chunk ^= (row>>1)&3.
// Single __syncthreads per K-stage: wait -> sync -> fill(s+3) -> compute(s).
#define HG_BM 128
#define HG_BN 128
#define HG_BK 32
#define HG_OFF_A  0
#define HG_OFF_BH 8192
#define HG_OFF_BL 16384
#define HG_STAGE  24576
#define HG_NSTAGE 4
#define HG_SMEM (HG_NSTAGE * HG_STAGE + 128)

__global__ __launch_bounds__(256, 2)
void hmma_gemm(const __half* __restrict__ A, int K,
               const __half* __restrict__ Bh, const __half* __restrict__ Bl,
               const float* __restrict__ bias,
               const float* __restrict__ addMat, const float* __restrict__ addScale,
               const float* __restrict__ residual,
               float* __restrict__ Cf, __half* __restrict__ Ch,
               int ldc)
{
    extern __shared__ char dsm[];
    uint32_t sbase = (smem_to_u32(dsm) + 127u) & ~127u;

    int tid  = threadIdx.x;
    int lane = tid & 31, warp = tid >> 5;
    int wm = warp >> 2, wn = warp & 3;       // warp tile: 64x32 at (wm*64, wn*32)
    int row0 = blockIdx.y * HG_BM;
    int col0 = blockIdx.x * HG_BN;

    // ---- fill geometry ----
    int frow = tid >> 1;                     // 0..127
    int fcb  = (tid & 1) * 2;                // chunk base 0 or 2
    uint32_t fsw = (uint32_t)((frow >> 1) & 3);
    uint32_t fs0 = (uint32_t)frow * 64 + (((uint32_t)fcb       ^ fsw) << 4);
    uint32_t fs1 = (uint32_t)frow * 64 + (((uint32_t)(fcb + 1) ^ fsw) << 4);
    const char* pA  = (const char*)(A  + (size_t)(row0 + frow) * K) + fcb * 16;
    const char* pBh = (const char*)(Bh + (size_t)(col0 + frow) * K) + fcb * 16;
    const char* pBl = (const char*)(Bl + (size_t)(col0 + frow) * K) + fcb * 16;

    // ---- ldmatrix geometry ----
    int r    = lane & 7;
    int tile = lane >> 3;
    int rowA_base = wm * 64 + ((tile & 1) << 3) + r;   // + mt*16
    int kcA       = tile >> 1;                          // 0 or 1
    int rowB_base = wn * 32 + ((tile >> 1) << 3) + r;  // + ng*16
    int kcB       = tile & 1;
    uint32_t swA = (uint32_t)((rowA_base >> 1) & 3);
    uint32_t swB = (uint32_t)((rowB_base >> 1) & 3);

    float acc[4][4][4];
    #pragma unroll
    for (int i = 0; i < 4; i++)
        #pragma unroll
        for (int j = 0; j < 4; j++)
            #pragma unroll
            for (int k = 0; k < 4; k++) acc[i][j][k] = 0.f;

    int NS = K / HG_BK;                      // >= 4 for all our GEMMs

    // prologue: fill stages 0..2
    #pragma unroll
    for (int p = 0; p < 3; p++) {
        uint32_t sb = sbase + p * HG_STAGE;
        size_t gk = (size_t)p * HG_BK * 2;   // byte offset along K
        CP_ASYNC16(sb + HG_OFF_A  + fs0, pA  + gk);
        CP_ASYNC16(sb + HG_OFF_A  + fs1, pA  + gk + 16);
        CP_ASYNC16(sb + HG_OFF_BH + fs0, pBh + gk);
        CP_ASYNC16(sb + HG_OFF_BH + fs1, pBh + gk + 16);
        CP_ASYNC16(sb + HG_OFF_BL + fs0, pBl + gk);
        CP_ASYNC16(sb + HG_OFF_BL + fs1, pBl + gk + 16);
        CP_COMMIT();
    }

    int buf = 0, fbuf = 3;
    for (int s = 0; s < NS; s++) {
        if (s + 2 < NS)      cp_wait<2>();
        else if (s + 1 < NS) cp_wait<1>();
        else                 cp_wait<0>();
        __syncthreads();

        // fill stage s+3 into fbuf = (s+3)%4 == (s-1)%4; its last readers
        // finished at iteration s-1, strictly before this barrier. Safe.
        if (s + 3 < NS) {
            uint32_t sb = sbase + fbuf * HG_STAGE;
            size_t gk = (size_t)(s + 3) * HG_BK * 2;
            CP_ASYNC16(sb + HG_OFF_A  + fs0, pA  + gk);
            CP_ASYNC16(sb + HG_OFF_A  + fs1, pA  + gk + 16);
            CP_ASYNC16(sb + HG_OFF_BH + fs0, pBh + gk);
            CP_ASYNC16(sb + HG_OFF_BH + fs1, pBh + gk + 16);
            CP_ASYNC16(sb + HG_OFF_BL + fs0, pBl + gk);
            CP_ASYNC16(sb + HG_OFF_BL + fs1, pBl + gk + 16);
            CP_COMMIT();
        }

        uint32_t sb = sbase + buf * HG_STAGE;
        #pragma unroll
        for (int ks = 0; ks < 2; ks++) {
            uint32_t a[4][4], bh[2][4], bl[2][4];
            uint32_t koA = ((((uint32_t)(ks * 2 + kcA)) ^ swA) << 4);
            uint32_t koB = ((((uint32_t)(ks * 2 + kcB)) ^ swB) << 4);
            #pragma unroll
            for (int mt = 0; mt < 4; mt++) {
                uint32_t rb = (uint32_t)(rowA_base + mt * 16) * 64;
                ldsm4(sb + HG_OFF_A + rb + koA, a[mt]);
            }
            #pragma unroll
            for (int ng = 0; ng < 2; ng++) {
                uint32_t rb = (uint32_t)(rowB_base + ng * 16) * 64;
                ldsm4(sb + HG_OFF_BH + rb + koB, bh[ng]);
                ldsm4(sb + HG_OFF_BL + rb + koB, bl[ng]);
            }
            #pragma unroll
            for (int mt = 0; mt < 4; mt++) {
                #pragma unroll
                for (int nt = 0; nt < 4; nt++) {
                    const uint32_t* bhp = &bh[nt >> 1][(nt & 1) * 2];
                    const uint32_t* blp = &bl[nt >> 1][(nt & 1) * 2];
                    mma16816(acc[mt][nt], a[mt], bhp);
                    mma16816(acc[mt][nt], a[mt], blp);
                }
            }
        }
        buf  = (buf == 3)  ? 0 : buf + 1;
        fbuf = (fbuf == 3) ? 0 : fbuf + 1;
    }

    // ---------- epilogue ----------
    int mbase = row0 + wm * 64 + (lane >> 2);
    int nbase = col0 + wn * 32 + ((lane & 3) << 1);
    #pragma unroll
    for (int mt = 0; mt < 4; mt++) {
        #pragma unroll
        for (int nt = 0; nt < 4; nt++) {
            int n = nbase + nt * 8;
            float b0 = 0.f, b1 = 0.f;
            if (bias) { b0 = bias[n]; b1 = bias[n + 1]; }
            #pragma unroll
            for (int h2 = 0; h2 < 2; h2++) {
                int m = mbase + mt * 16 + h2 * 8;
                size_t off = (size_t)m * ldc + n;
                float v0 = acc[mt][nt][h2 * 2 + 0] + b0;
                float v1 = acc[mt][nt][h2 * 2 + 1] + b1;
                if (addMat) {
                    float2 mm = *(const float2*)(addMat + off);
                    v0 += addScale[n]     * mm.x;
                    v1 += addScale[n + 1] * mm.y;
                }
                if (residual) {
                    float2 rr = *(const float2*)(residual + off);
                    v0 += rr.x; v1 += rr.y;
                }
                if (Cf) { float2 o; o.x = v0; o.y = v1; *(float2*)(Cf + off) = o; }
                if (Ch) {
                    __half2 p;
                    p.x = __float2half_rn(v0); p.y = __float2half_rn(v1);
                    *(__half2*)(Ch + off) = p;
                }
            }
        }
    }
}

// ---------------- chunked linear scan: y[t] = r*y[t-1] + xs[t]*B[t] ----------------
__global__ void scan1_kernel(const float* __restrict__ zcat, const float* __restrict__ A_log,
                             float* __restrict__ yloc, float* __restrict__ carry)
{
    int b = blockIdx.x / NCHUNK;
    int c = blockIdx.x % NCHUNK;
    int s = threadIdx.x;                             // 0..127
    float r = expf(-expf(A_log[s]));
    size_t row = (size_t)b * LSEQ + (size_t)c * CHUNK;
    const float* zp = zcat + row * NCAT;
    float* yp = yloc + row * DSTATE;
    float acc = 0.f;
    #pragma unroll 4
    for (int i = 0; i < CHUNK; i++) {
        float xs = zp[(size_t)i * NCAT + s];
        float bb = zp[(size_t)i * NCAT + 128 + s];
        acc = acc * r + xs * bb;
        yp[i * DSTATE + s] = acc;
    }
    carry[((size_t)b * NCHUNK + c) * DSTATE + s] = acc;
}

// compute chunk prefix from carries locally, inject, multiply by C_sel, emit ys fp16
__global__ void scan3_kernel(const float* __restrict__ yloc, const float* __restrict__ carry,
                             const float* __restrict__ zcat, const float* __restrict__ A_log,
                             __half* __restrict__ ysf)
{
    int b = blockIdx.x / NCHUNK;
    int c = blockIdx.x % NCHUNK;
    int s = threadIdx.x;
    float a  = -expf(A_log[s]);
    float r  = expf(a);
    float rC = expf(a * (float)CHUNK);
    float st = 0.f;
    for (int j = 0; j < c; j++)
        st = st * rC + carry[((size_t)b * NCHUNK + j) * DSTATE + s];
    float p = st;
    size_t row = (size_t)b * LSEQ + (size_t)c * CHUNK;
    const float* yp = yloc + row * DSTATE;
    const float* cp = zcat + row * NCAT + 256;       // C_sel columns
    size_t obase = row * DSTATE;
    #pragma unroll 4
    for (int i = 0; i < CHUNK; i++) {
        p *= r;
        float v = (yp[i * DSTATE + s] + p) * cp[(size_t)i * NCAT + s];
        ysf[obase + i * DSTATE + s] = __float2half_rn(v);
    }
}

// ---------------- host ----------------
static float* sym_addr_f(const void* symbol)
{
    void* p = nullptr;
    cudaGetSymbolAddress(&p, symbol);
    return (float*)p;
}
static __half* sym_addr_h(const void* symbol)
{
    void* p = nullptr;
    cudaGetSymbolAddress(&p, symbol);
    return (__half*)p;
}

extern "C" void kernel_launch(void* const* d_in, const int* in_sizes, int n_in,
                              void* d_out, int out_size)
{
    (void)in_sizes; (void)n_in; (void)out_size;
    const float* x      = (const float*)d_in[0];
    const float* ln_g   = (const float*)d_in[1];
    const float* ln_b   = (const float*)d_in[2];
    const float* W_in   = (const float*)d_in[3];
    const float* b_in   = (const float*)d_in[4];
    const float* W_xs   = (const float*)d_in[5];
    const float* W_B    = (const float*)d_in[6];
    const float* b_B    = (const float*)d_in[7];
    const float* W_C    = (const float*)d_in[8];
    const float* b_C    = (const float*)d_in[9];
    const float* A_log  = (const float*)d_in[10];
    const float* Dvec   = (const float*)d_in[11];
    const float* W_so   = (const float*)d_in[12];
    const float* W_out  = (const float*)d_in[13];
    const float* b_out  = (const float*)d_in[14];
    float* out = (float*)d_out;

    float* z     = sym_addr_f(g_z);
    float* zcat  = sym_addr_f(g_zcat);
    float* yloc  = sym_addr_f(g_yloc);
    float* carry = sym_addr_f(g_carry);
    float* bcat  = sym_addr_f(g_bcat);
    __half* xnf = sym_addr_h(g_xnf);
    __half* zf  = sym_addr_h(g_zf);
    __half* yf  = sym_addr_h(g_yf);
    __half* ysf = sym_addr_h(g_ysf);
    __half* WinT_h  = sym_addr_h(g_WinT_h);
    __half* WinT_l  = sym_addr_h(g_WinT_l);
    __half* WoutT_h = sym_addr_h(g_WoutT_h);
    __half* WoutT_l = sym_addr_h(g_WoutT_l);
    __half* WsoT_h  = sym_addr_h(g_WsoT_h);
    __half* WsoT_l  = sym_addr_h(g_WsoT_l);
    __half* WcatT_h = sym_addr_h(g_WcatT_h);
    __half* WcatT_l = sym_addr_h(g_WcatT_l);

    cudaFuncSetAttribute(hmma_gemm, cudaFuncAttributeMaxDynamicSharedMemorySize, HG_SMEM);

    // fused weight prep (1 launch)
    prep_kernel<<<dim3(32, 32, 3), dim3(32, 8)>>>(
        W_in, W_out, W_so, W_xs, W_B, W_C, b_B, b_C,
        WinT_h, WinT_l, WoutT_h, WoutT_l, WsoT_h, WsoT_l, WcatT_h, WcatT_l, bcat);

    // LayerNorm -> xn (fp16)
    ln_kernel<<<MROWS, 256>>>(x, ln_g, ln_b, xnf);

    // z = xn @ W_in + b_in   (fp32 z for D-skip, fp16 z for next GEMMs)
    hmma_gemm<<<dim3(DMODEL / HG_BN, MROWS / HG_BM), 256, HG_SMEM>>>(
        xnf, DMODEL, WinT_h, WinT_l, b_in,
        nullptr, nullptr, nullptr, z, zf, DMODEL);

    // fused projections: zcat = z @ [W_xs | W_B | W_C | 0] + bcat  (fp32)
    hmma_gemm<<<dim3(NCAT / HG_BN, MROWS / HG_BM), 256, HG_SMEM>>>(
        zf, DMODEL, WcatT_h, WcatT_l, bcat,
        nullptr, nullptr, nullptr, zcat, nullptr, NCAT);

    // chunked linear scan (u = xs*Bsel fused in scan1; prefix + *C_sel in scan3)
    scan1_kernel<<<NBATCH * NCHUNK, DSTATE>>>(zcat, A_log, yloc, carry);
    scan3_kernel<<<NBATCH * NCHUNK, DSTATE>>>(yloc, carry, zcat, A_log, ysf);

    // y = ys @ W_so + D * z   (fp16 y only)
    hmma_gemm<<<dim3(DMODEL / HG_BN, MROWS / HG_BM), 256, HG_SMEM>>>(
        ysf, DSTATE, WsoT_h, WsoT_l, nullptr,
        z, Dvec, nullptr, nullptr, yf, DMODEL);

    // out = y @ W_out + b_out + x
    hmma_gemm<<<dim3(DMODEL / HG_BN, MROWS / HG_BM), 256, HG_SMEM>>>(
        yf, DMODEL, WoutT_h, WoutT_l, b_out,
        nullptr, nullptr, x, out, nullptr, DMODEL);
}

// round 14
// speedup vs baseline: 1.9591x; 1.0209x over previous
#include <cuda_runtime.h>
#include <cuda_fp16.h>
#include <math.h>
#include <stdint.h>

// ---------------- problem constants ----------------
#define DMODEL 1024
#define DSTATE 128
#define LSEQ   4096
#define NBATCH 4
#define MROWS  (NBATCH * LSEQ)   // 16384
#define LN_EPS 1e-3f

#define CHUNK  64
#define NCHUNK (LSEQ / CHUNK)    // 64
#define NCAT   512               // padded 3*128 fused projection width

// ---------------- portable PTX helpers (sm_80+ features only) ----------------
__device__ __forceinline__ uint32_t smem_to_u32(const void* smem_ptr) {
    uint32_t addr;
    asm("{ .reg .u64 tmp; cvta.to.shared.u64 tmp, %1; cvt.u32.u64 %0, tmp; }"
        : "=r"(addr) : "l"(smem_ptr));
    return addr;
}

#define CP_ASYNC16(smem_u32, gptr) \
    asm volatile("cp.async.cg.shared.global [%0], [%1], 16;" \
        :: "r"(smem_u32), "l"(gptr) : "memory")
#define CP_COMMIT() asm volatile("cp.async.commit_group;" ::: "memory")

template <int N>
__device__ __forceinline__ void cp_wait() {
    asm volatile("cp.async.wait_group %0;" :: "n"(N) : "memory");
}

__device__ __forceinline__ void ldsm4(uint32_t addr, uint32_t* r) {
    asm volatile("ldmatrix.sync.aligned.m8n8.x4.shared.b16 {%0,%1,%2,%3}, [%4];"
        : "=r"(r[0]), "=r"(r[1]), "=r"(r[2]), "=r"(r[3]) : "r"(addr));
}

// fp16 inputs, fp32 accumulate
__device__ __forceinline__ void mma16816(float* c, const uint32_t* a, const uint32_t* b) {
    asm volatile(
        "mma.sync.aligned.m16n8k16.row.col.f32.f16.f16.f32 "
        "{%0,%1,%2,%3}, {%4,%5,%6,%7}, {%8,%9}, {%0,%1,%2,%3};"
        : "+f"(c[0]), "+f"(c[1]), "+f"(c[2]), "+f"(c[3])
        : "r"(a[0]), "r"(a[1]), "r"(a[2]), "r"(a[3]), "r"(b[0]), "r"(b[1]));
}

// fp16 2-term split: h captures 11 bits, l the next 11 -> ~22-bit weight precision
__device__ __forceinline__ void split1h(float v, __half& h, __half& l) {
    h = __float2half_rn(v);
    l = __float2half_rn(v - __half2float(h));
}

// ---------------- scratch (static device globals; no allocation) ----------------
__device__ float g_z   [(size_t)MROWS * DMODEL];
__device__ float g_zcat[(size_t)MROWS * NCAT];
__device__ float g_yloc[(size_t)MROWS * DSTATE];
__device__ float g_carry[NBATCH * NCHUNK * DSTATE];
// fp16 activations (single copy)
__device__ __half g_xnf[(size_t)MROWS * DMODEL];
__device__ __half g_zf [(size_t)MROWS * DMODEL];
__device__ __half g_yf [(size_t)MROWS * DMODEL];
__device__ __half g_ysf[(size_t)MROWS * DSTATE];
// pre-transposed, fp16-split weights ([N, K] layout, K-major)
__device__ __half g_WinT_h [(size_t)DMODEL * DMODEL];
__device__ __half g_WinT_l [(size_t)DMODEL * DMODEL];
__device__ __half g_WoutT_h[(size_t)DMODEL * DMODEL];
__device__ __half g_WoutT_l[(size_t)DMODEL * DMODEL];
__device__ __half g_WsoT_h [(size_t)DMODEL * DSTATE];
__device__ __half g_WsoT_l [(size_t)DMODEL * DSTATE];
__device__ __half g_WcatT_h[(size_t)NCAT * DMODEL];
__device__ __half g_WcatT_l[(size_t)NCAT * DMODEL];
__device__ float g_bcat[NCAT];

// ---------------- LayerNorm (emits fp16 directly) ----------------
__global__ void ln_kernel(const float* __restrict__ x,
                          const float* __restrict__ gamma,
                          const float* __restrict__ beta,
                          __half* __restrict__ of)
{
    int row = blockIdx.x;
    const float4* xr = (const float4*)(x + (size_t)row * DMODEL);
    float4 v = xr[threadIdx.x];
    float s = v.x + v.y + v.z + v.w;
    float q = v.x * v.x + v.y * v.y + v.z * v.z + v.w * v.w;
    #pragma unroll
    for (int o = 16; o; o >>= 1) {
        s += __shfl_xor_sync(0xffffffffu, s, o);
        q += __shfl_xor_sync(0xffffffffu, q, o);
    }
    __shared__ float ss[8], sq[8];
    int w = threadIdx.x >> 5;
    if ((threadIdx.x & 31) == 0) { ss[w] = s; sq[w] = q; }
    __syncthreads();
    s = 0.f; q = 0.f;
    #pragma unroll
    for (int i = 0; i < 8; i++) { s += ss[i]; q += sq[i]; }
    float mu  = s * (1.0f / DMODEL);
    float var = q * (1.0f / DMODEL) - mu * mu;
    float inv = rsqrtf(var + LN_EPS);
    float4 gv = ((const float4*)gamma)[threadIdx.x];
    float4 bv = ((const float4*)beta)[threadIdx.x];
    float r0 = (v.x - mu) * inv * gv.x + bv.x;
    float r1 = (v.y - mu) * inv * gv.y + bv.y;
    float r2 = (v.z - mu) * inv * gv.z + bv.z;
    float r3 = (v.w - mu) * inv * gv.w + bv.w;
    size_t o = (size_t)row * DMODEL + threadIdx.x * 4;
    __half2 p;
    p.x = __float2half_rn(r0); p.y = __float2half_rn(r1);
    *(__half2*)(of + o) = p;
    p.x = __float2half_rn(r2); p.y = __float2half_rn(r3);
    *(__half2*)(of + o + 2) = p;
}

// ---------------- fused weight prep: transpose + fp16-split + pad + bcat ----------------
__device__ __forceinline__ void tsplit_body(const float* __restrict__ W,
                                            __half* __restrict__ Th,
                                            __half* __restrict__ Tl,
                                            int N, int rowOff, int ldT,
                                            int n0, int k0, float sm[32][33])
{
    int tx = threadIdx.x, ty = threadIdx.y;          // 32 x 8
    #pragma unroll
    for (int j = 0; j < 32; j += 8)
        sm[ty + j][tx] = W[(size_t)(k0 + ty + j) * N + n0 + tx];
    __syncthreads();
    #pragma unroll
    for (int j = 0; j < 32; j += 8) {
        int n = ty + j;
        float v = sm[tx][n];                         // W[k0+tx][n0+n]
        __half h, l;
        split1h(v, h, l);
        size_t o = (size_t)(rowOff + n0 + n) * ldT + k0 + tx;
        Th[o] = h; Tl[o] = l;
    }
}

// grid (32, 32, 3), block (32, 8)
__global__ void prep_kernel(const float* __restrict__ W_in,  const float* __restrict__ W_out,
                            const float* __restrict__ W_so,
                            const float* __restrict__ W_xs,  const float* __restrict__ W_B,
                            const float* __restrict__ W_C,
                            const float* __restrict__ bB,    const float* __restrict__ bC,
                            __half* WinT_h,  __half* WinT_l,
                            __half* WoutT_h, __half* WoutT_l,
                            __half* WsoT_h,  __half* WsoT_l,
                            __half* WcatT_h, __half* WcatT_l,
                            float* __restrict__ bcat)
{
    __shared__ float sm[32][33];
    int z = blockIdx.z;
    if (z == 0) {
        tsplit_body(W_in, WinT_h, WinT_l, DMODEL, 0, DMODEL,
                    (int)blockIdx.x * 32, (int)blockIdx.y * 32, sm);
    } else if (z == 1) {
        tsplit_body(W_out, WoutT_h, WoutT_l, DMODEL, 0, DMODEL,
                    (int)blockIdx.x * 32, (int)blockIdx.y * 32, sm);
    } else {
        int idx = (int)blockIdx.x + 32 * (int)blockIdx.y;    // 0..1023
        if (idx < 128) {
            int bx = idx & 31, by = idx >> 5;
            tsplit_body(W_so, WsoT_h, WsoT_l, DMODEL, 0, DSTATE, bx * 32, by * 32, sm);
        } else if (idx < 512) {
            int j = idx - 128;                   // 0..383
            int w = j >> 7;                      // 0..2
            int rr = j & 127;
            int bx = rr & 3, by = rr >> 2;
            const float* W = (w == 0) ? W_xs : (w == 1) ? W_B : W_C;
            tsplit_body(W, WcatT_h, WcatT_l, DSTATE, w * 128, DMODEL, bx * 32, by * 32, sm);
        } else {
            int i = (idx - 512) * 256 + (int)threadIdx.y * 32 + (int)threadIdx.x;
            __half zv = __float2half_rn(0.f);
            WcatT_h[(size_t)384 * DMODEL + i] = zv;
            WcatT_l[(size_t)384 * DMODEL + i] = zv;
            if (i < NCAT) {
                float v = 0.f;
                if (i >= 128 && i < 256) v = bB[i - 128];
                else if (i >= 256 && i < 384) v = bC[i - 256];
                bcat[i] = v;
            }
        }
    }
}

// ---------------- HMMA fp16 weight-split GEMM (128x128 tile, BK=32, 4 stages, occ 2) ----------------
// C = A @ B^T, A=[M,K] single fp16, B=[N,K] fp16.
// If Bl != nullptr: B is 2-split (Bh+Bl), C = A@Bh + A@Bl  (exact-weight path).
// If Bl == nullptr: single-weight path, C = A@Bh        (1 MMA per fragment pair).
// 256 threads, 8 warps (2x4), 64x32 warp tile. 64B rows, swizzle: chunk ^= (row>>1)&3.
// Single __syncthreads per K-stage: wait -> sync -> fill(s+3) -> compute(s).
#define HG_BM 128
#define HG_BN 128
#define HG_BK 32
#define HG_OFF_A  0
#define HG_OFF_BH 8192
#define HG_OFF_BL 16384
#define HG_STAGE  24576
#define HG_NSTAGE 4
#define HG_SMEM (HG_NSTAGE * HG_STAGE + 128)

__global__ __launch_bounds__(256, 2)
void hmma_gemm(const __half* __restrict__ A, int K,
               const __half* __restrict__ Bh, const __half* __restrict__ Bl,
               const float* __restrict__ bias,
               const float* __restrict__ addMat, const float* __restrict__ addScale,
               const float* __restrict__ residual,
               float* __restrict__ Cf, __half* __restrict__ Ch,
               int ldc)
{
    extern __shared__ char dsm[];
    uint32_t sbase = (smem_to_u32(dsm) + 127u) & ~127u;

    int tid  = threadIdx.x;
    int lane = tid & 31, warp = tid >> 5;
    int wm = warp >> 2, wn = warp & 3;       // warp tile: 64x32 at (wm*64, wn*32)
    int row0 = blockIdx.y * HG_BM;
    int col0 = blockIdx.x * HG_BN;
    const bool ubl = (Bl != nullptr);

    // ---- fill geometry ----
    int frow = tid >> 1;                     // 0..127
    int fcb  = (tid & 1) * 2;                // chunk base 0 or 2
    uint32_t fsw = (uint32_t)((frow >> 1) & 3);
    uint32_t fs0 = (uint32_t)frow * 64 + (((uint32_t)fcb       ^ fsw) << 4);
    uint32_t fs1 = (uint32_t)frow * 64 + (((uint32_t)(fcb + 1) ^ fsw) << 4);
    const char* pA  = (const char*)(A  + (size_t)(row0 + frow) * K) + fcb * 16;
    const char* pBh = (const char*)(Bh + (size_t)(col0 + frow) * K) + fcb * 16;
    const char* pBl = ubl ? (const char*)(Bl + (size_t)(col0 + frow) * K) + fcb * 16 : pBh;

    // ---- ldmatrix geometry ----
    int r    = lane & 7;
    int tile = lane >> 3;
    int rowA_base = wm * 64 + ((tile & 1) << 3) + r;   // + mt*16
    int kcA       = tile >> 1;                          // 0 or 1
    int rowB_base = wn * 32 + ((tile >> 1) << 3) + r;  // + ng*16
    int kcB       = tile & 1;
    uint32_t swA = (uint32_t)((rowA_base >> 1) & 3);
    uint32_t swB = (uint32_t)((rowB_base >> 1) & 3);

    float acc[4][4][4];
    #pragma unroll
    for (int i = 0; i < 4; i++)
        #pragma unroll
        for (int j = 0; j < 4; j++)
            #pragma unroll
            for (int k = 0; k < 4; k++) acc[i][j][k] = 0.f;

    int NS = K / HG_BK;                      // >= 4 for all our GEMMs

    // prologue: fill stages 0..2
    #pragma unroll
    for (int p = 0; p < 3; p++) {
        uint32_t sb = sbase + p * HG_STAGE;
        size_t gk = (size_t)p * HG_BK * 2;   // byte offset along K
        CP_ASYNC16(sb + HG_OFF_A  + fs0, pA  + gk);
        CP_ASYNC16(sb + HG_OFF_A  + fs1, pA  + gk + 16);
        CP_ASYNC16(sb + HG_OFF_BH + fs0, pBh + gk);
        CP_ASYNC16(sb + HG_OFF_BH + fs1, pBh + gk + 16);
        if (ubl) {
            CP_ASYNC16(sb + HG_OFF_BL + fs0, pBl + gk);
            CP_ASYNC16(sb + HG_OFF_BL + fs1, pBl + gk + 16);
        }
        CP_COMMIT();
    }

    int buf = 0, fbuf = 3;
    for (int s = 0; s < NS; s++) {
        if (s + 2 < NS)      cp_wait<2>();
        else if (s + 1 < NS) cp_wait<1>();
        else                 cp_wait<0>();
        __syncthreads();

        // fill stage s+3 into fbuf = (s+3)%4 == (s-1)%4; its last readers
        // finished at iteration s-1, strictly before this barrier. Safe.
        if (s + 3 < NS) {
            uint32_t sb = sbase + fbuf * HG_STAGE;
            size_t gk = (size_t)(s + 3) * HG_BK * 2;
            CP_ASYNC16(sb + HG_OFF_A  + fs0, pA  + gk);
            CP_ASYNC16(sb + HG_OFF_A  + fs1, pA  + gk + 16);
            CP_ASYNC16(sb + HG_OFF_BH + fs0, pBh + gk);
            CP_ASYNC16(sb + HG_OFF_BH + fs1, pBh + gk + 16);
            if (ubl) {
                CP_ASYNC16(sb + HG_OFF_BL + fs0, pBl + gk);
                CP_ASYNC16(sb + HG_OFF_BL + fs1, pBl + gk + 16);
            }
            CP_COMMIT();
        }

        uint32_t sb = sbase + buf * HG_STAGE;
        #pragma unroll
        for (int ks = 0; ks < 2; ks++) {
            uint32_t a[4][4], bh[2][4], bl[2][4];
            uint32_t koA = ((((uint32_t)(ks * 2 + kcA)) ^ swA) << 4);
            uint32_t koB = ((((uint32_t)(ks * 2 + kcB)) ^ swB) << 4);
            #pragma unroll
            for (int mt = 0; mt < 4; mt++) {
                uint32_t rb = (uint32_t)(rowA_base + mt * 16) * 64;
                ldsm4(sb + HG_OFF_A + rb + koA, a[mt]);
            }
            #pragma unroll
            for (int ng = 0; ng < 2; ng++) {
                uint32_t rb = (uint32_t)(rowB_base + ng * 16) * 64;
                ldsm4(sb + HG_OFF_BH + rb + koB, bh[ng]);
                if (ubl) ldsm4(sb + HG_OFF_BL + rb + koB, bl[ng]);
            }
            #pragma unroll
            for (int mt = 0; mt < 4; mt++) {
                #pragma unroll
                for (int nt = 0; nt < 4; nt++) {
                    const uint32_t* bhp = &bh[nt >> 1][(nt & 1) * 2];
                    mma16816(acc[mt][nt], a[mt], bhp);
                    if (ubl) {
                        const uint32_t* blp = &bl[nt >> 1][(nt & 1) * 2];
                        mma16816(acc[mt][nt], a[mt], blp);
                    }
                }
            }
        }
        buf  = (buf == 3)  ? 0 : buf + 1;
        fbuf = (fbuf == 3) ? 0 : fbuf + 1;
    }

    // ---------- epilogue ----------
    int mbase = row0 + wm * 64 + (lane >> 2);
    int nbase = col0 + wn * 32 + ((lane & 3) << 1);
    #pragma unroll
    for (int mt = 0; mt < 4; mt++) {
        #pragma unroll
        for (int nt = 0; nt < 4; nt++) {
            int n = nbase + nt * 8;
            float b0 = 0.f, b1 = 0.f;
            if (bias) { b0 = bias[n]; b1 = bias[n + 1]; }
            #pragma unroll
            for (int h2 = 0; h2 < 2; h2++) {
                int m = mbase + mt * 16 + h2 * 8;
                size_t off = (size_t)m * ldc + n;
                float v0 = acc[mt][nt][h2 * 2 + 0] + b0;
                float v1 = acc[mt][nt][h2 * 2 + 1] + b1;
                if (addMat) {
                    float2 mm = *(const float2*)(addMat + off);
                    v0 += addScale[n]     * mm.x;
                    v1 += addScale[n + 1] * mm.y;
                }
                if (residual) {
                    float2 rr = *(const float2*)(residual + off);
                    v0 += rr.x; v1 += rr.y;
                }
                if (Cf) { float2 o; o.x = v0; o.y = v1; *(float2*)(Cf + off) = o; }
                if (Ch) {
                    __half2 p;
                    p.x = __float2half_rn(v0); p.y = __float2half_rn(v1);
                    *(__half2*)(Ch + off) = p;
                }
            }
        }
    }
}

// ---------------- chunked linear scan: y[t] = r*y[t-1] + xs[t]*B[t] ----------------
__global__ void scan1_kernel(const float* __restrict__ zcat, const float* __restrict__ A_log,
                             float* __restrict__ yloc, float* __restrict__ carry)
{
    int b = blockIdx.x / NCHUNK;
    int c = blockIdx.x % NCHUNK;
    int s = threadIdx.x;                             // 0..127
    float r = expf(-expf(A_log[s]));
    size_t row = (size_t)b * LSEQ + (size_t)c * CHUNK;
    const float* zp = zcat + row * NCAT;
    float* yp = yloc + row * DSTATE;
    float acc = 0.f;
    #pragma unroll 4
    for (int i = 0; i < CHUNK; i++) {
        float xs = zp[(size_t)i * NCAT + s];
        float bb = zp[(size_t)i * NCAT + 128 + s];
        acc = acc * r + xs * bb;
        yp[i * DSTATE + s] = acc;
    }
    carry[((size_t)b * NCHUNK + c) * DSTATE + s] = acc;
}

// compute chunk prefix from carries locally, inject, multiply by C_sel, emit ys fp16
__global__ void scan3_kernel(const float* __restrict__ yloc, const float* __restrict__ carry,
                             const float* __restrict__ zcat, const float* __restrict__ A_log,
                             __half* __restrict__ ysf)
{
    int b = blockIdx.x / NCHUNK;
    int c = blockIdx.x % NCHUNK;
    int s = threadIdx.x;
    float a  = -expf(A_log[s]);
    float r  = expf(a);
    float rC = expf(a * (float)CHUNK);
    float st = 0.f;
    for (int j = 0; j < c; j++)
        st = st * rC + carry[((size_t)b * NCHUNK + j) * DSTATE + s];
    float p = st;
    size_t row = (size_t)b * LSEQ + (size_t)c * CHUNK;
    const float* yp = yloc + row * DSTATE;
    const float* cp = zcat + row * NCAT + 256;       // C_sel columns
    size_t obase = row * DSTATE;
    #pragma unroll 4
    for (int i = 0; i < CHUNK; i++) {
        p *= r;
        float v = (yp[i * DSTATE + s] + p) * cp[(size_t)i * NCAT + s];
        ysf[obase + i * DSTATE + s] = __float2half_rn(v);
    }
}

// ---------------- host ----------------
static float* sym_addr_f(const void* symbol)
{
    void* p = nullptr;
    cudaGetSymbolAddress(&p, symbol);
    return (float*)p;
}
static __half* sym_addr_h(const void* symbol)
{
    void* p = nullptr;
    cudaGetSymbolAddress(&p, symbol);
    return (__half*)p;
}

extern "C" void kernel_launch(void* const* d_in, const int* in_sizes, int n_in,
                              void* d_out, int out_size)
{
    (void)in_sizes; (void)n_in; (void)out_size;
    const float* x      = (const float*)d_in[0];
    const float* ln_g   = (const float*)d_in[1];
    const float* ln_b   = (const float*)d_in[2];
    const float* W_in   = (const float*)d_in[3];
    const float* b_in   = (const float*)d_in[4];
    const float* W_xs   = (const float*)d_in[5];
    const float* W_B    = (const float*)d_in[6];
    const float* b_B    = (const float*)d_in[7];
    const float* W_C    = (const float*)d_in[8];
    const float* b_C    = (const float*)d_in[9];
    const float* A_log  = (const float*)d_in[10];
    const float* Dvec   = (const float*)d_in[11];
    const float* W_so   = (const float*)d_in[12];
    const float* W_out  = (const float*)d_in[13];
    const float* b_out  = (const float*)d_in[14];
    float* out = (float*)d_out;

    float* z     = sym_addr_f(g_z);
    float* zcat  = sym_addr_f(g_zcat);
    float* yloc  = sym_addr_f(g_yloc);
    float* carry = sym_addr_f(g_carry);
    float* bcat  = sym_addr_f(g_bcat);
    __half* xnf = sym_addr_h(g_xnf);
    __half* zf  = sym_addr_h(g_zf);
    __half* yf  = sym_addr_h(g_yf);
    __half* ysf = sym_addr_h(g_ysf);
    __half* WinT_h  = sym_addr_h(g_WinT_h);
    __half* WinT_l  = sym_addr_h(g_WinT_l);
    __half* WoutT_h = sym_addr_h(g_WoutT_h);
    __half* WoutT_l = sym_addr_h(g_WoutT_l);
    __half* WsoT_h  = sym_addr_h(g_WsoT_h);
    __half* WsoT_l  = sym_addr_h(g_WsoT_l);
    __half* WcatT_h = sym_addr_h(g_WcatT_h);
    __half* WcatT_l = sym_addr_h(g_WcatT_l);
    (void)WoutT_l; (void)WsoT_l;

    cudaFuncSetAttribute(hmma_gemm, cudaFuncAttributeMaxDynamicSharedMemorySize, HG_SMEM);

    // fused weight prep (1 launch)
    prep_kernel<<<dim3(32, 32, 3), dim3(32, 8)>>>(
        W_in, W_out, W_so, W_xs, W_B, W_C, b_B, b_C,
        WinT_h, WinT_l, WoutT_h, WoutT_l, WsoT_h, WsoT_l, WcatT_h, WcatT_l, bcat);

    // LayerNorm -> xn (fp16)
    ln_kernel<<<MROWS, 256>>>(x, ln_g, ln_b, xnf);

    // G1: z = xn @ W_in + b_in    (exact-weight 2-MMA path; errors feed the scan)
    hmma_gemm<<<dim3(DMODEL / HG_BN, MROWS / HG_BM), 256, HG_SMEM>>>(
        xnf, DMODEL, WinT_h, WinT_l, b_in,
        nullptr, nullptr, nullptr, z, zf, DMODEL);

    // G2: zcat = z @ [W_xs | W_B | W_C | 0] + bcat   (exact-weight 2-MMA path)
    hmma_gemm<<<dim3(NCAT / HG_BN, MROWS / HG_BM), 256, HG_SMEM>>>(
        zf, DMODEL, WcatT_h, WcatT_l, bcat,
        nullptr, nullptr, nullptr, zcat, nullptr, NCAT);

    // chunked linear scan (u = xs*Bsel fused in scan1; prefix + *C_sel in scan3)
    scan1_kernel<<<NBATCH * NCHUNK, DSTATE>>>(zcat, A_log, yloc, carry);
    scan3_kernel<<<NBATCH * NCHUNK, DSTATE>>>(yloc, carry, zcat, A_log, ysf);

    // G3: y = ys @ W_so + D * z   (single-weight 1-MMA path; output-side error)
    hmma_gemm<<<dim3(DMODEL / HG_BN, MROWS / HG_BM), 256, HG_SMEM>>>(
        ysf, DSTATE, WsoT_h, nullptr, nullptr,
        z, Dvec, nullptr, nullptr, yf, DMODEL);

    // G4: out = y @ W_out + b_out + x   (single-weight 1-MMA path)
    hmma_gemm<<<dim3(DMODEL / HG_BN, MROWS / HG_BM), 256, HG_SMEM>>>(
        yf, DMODEL, WoutT_h, nullptr, b_out,
        nullptr, nullptr, x, out, nullptr, DMODEL);
}